// round 1
// baseline (speedup 1.0000x reference)
#include <cuda_runtime.h>

#define S_TOT  2560
#define S_TXTC 512
#define S_IMGC 2048
#define DIMK   3072
#define NHEADS 24
#define HDIM   128
#define E3     9216
#define EPSV   1e-6f
#define QSCALE 0.088388347648318447f   // 1/sqrt(128)

// ---------------- scratch (device globals; no allocation allowed) ----------
static __device__ float g_qkv[S_TOT * E3];                 // raw qkv, rows 0..511 txt, 512.. img
static __device__ float g_Q[NHEADS * S_TOT * HDIM];        // [h][s][d], pre-scaled by 1/sqrt(D)
static __device__ float g_K[NHEADS * S_TOT * HDIM];
static __device__ float g_V[NHEADS * S_TOT * HDIM];
static __device__ float g_O[S_TOT * DIMK];                 // attention out, [s][h*D+d]

// ---------------- shared SGEMM mainloop (M,N tiles 128, K=3072, BK=16) -----
// C[m,n] = sum_k A[m,k] * W[n,k]   (both operands K-contiguous, NT GEMM)
__device__ __forceinline__ void sgemm_main(const float* __restrict__ A,
                                           const float* __restrict__ W,
                                           float (&acc)[8][8],
                                           float* As, float* Bs, int t)
{
    const int tx = t & 15, ty = t >> 4;
    for (int k0 = 0; k0 < DIMK; k0 += 16) {
#pragma unroll
        for (int l = 0; l < 2; l++) {
            int i = t + (l << 8);
            int r = i >> 2;             // 0..127
            int c = (i & 3) << 2;       // 0,4,8,12
            float4 va = *(const float4*)(A + (size_t)r * DIMK + k0 + c);
            As[(c + 0) * 128 + r] = va.x;
            As[(c + 1) * 128 + r] = va.y;
            As[(c + 2) * 128 + r] = va.z;
            As[(c + 3) * 128 + r] = va.w;
            float4 vb = *(const float4*)(W + (size_t)r * DIMK + k0 + c);
            Bs[(c + 0) * 128 + r] = vb.x;
            Bs[(c + 1) * 128 + r] = vb.y;
            Bs[(c + 2) * 128 + r] = vb.z;
            Bs[(c + 3) * 128 + r] = vb.w;
        }
        __syncthreads();
#pragma unroll
        for (int k = 0; k < 16; k++) {
            float a[8], b[8];
            *(float4*)&a[0] = *(float4*)&As[k * 128 + ty * 4];
            *(float4*)&a[4] = *(float4*)&As[k * 128 + 64 + ty * 4];
            *(float4*)&b[0] = *(float4*)&Bs[k * 128 + tx * 4];
            *(float4*)&b[4] = *(float4*)&Bs[k * 128 + 64 + tx * 4];
#pragma unroll
            for (int i = 0; i < 8; i++)
#pragma unroll
                for (int j = 0; j < 8; j++)
                    acc[i][j] = fmaf(a[i], b[j], acc[i][j]);
        }
        __syncthreads();
    }
}

// ---------------- kernel 1: fused QKV projection -------------------------
__global__ __launch_bounds__(256) void gemm_qkv_kernel(
    const float* __restrict__ x_img, const float* __restrict__ x_txt,
    const float* __restrict__ w_img, const float* __restrict__ b_img,
    const float* __restrict__ w_txt, const float* __restrict__ b_txt)
{
    __shared__ float As[16 * 128];
    __shared__ float Bs[16 * 128];
    const int m0 = blockIdx.y * 128;
    const int n0 = blockIdx.x * 128;
    const bool txt = (m0 < S_TXTC);
    const float* A    = txt ? (x_txt + (size_t)m0 * DIMK)
                            : (x_img + (size_t)(m0 - S_TXTC) * DIMK);
    const float* W    = (txt ? w_txt : w_img) + (size_t)n0 * DIMK;
    const float* bias = (txt ? b_txt : b_img) + n0;

    const int t = threadIdx.x;
    const int tx = t & 15, ty = t >> 4;
    float acc[8][8];
#pragma unroll
    for (int i = 0; i < 8; i++)
#pragma unroll
        for (int j = 0; j < 8; j++) acc[i][j] = 0.f;

    sgemm_main(A, W, acc, As, Bs, t);

#pragma unroll
    for (int i = 0; i < 8; i++) {
        int rloc = (i < 4) ? (ty * 4 + i) : (64 + ty * 4 + i - 4);
        float* Crow = g_qkv + (size_t)(m0 + rloc) * E3 + n0;
#pragma unroll
        for (int half = 0; half < 2; half++) {
            int cb = half * 64 + tx * 4;
            float4 v;
            v.x = acc[i][half * 4 + 0] + bias[cb + 0];
            v.y = acc[i][half * 4 + 1] + bias[cb + 1];
            v.z = acc[i][half * 4 + 2] + bias[cb + 2];
            v.w = acc[i][half * 4 + 3] + bias[cb + 3];
            *(float4*)(Crow + cb) = v;
        }
    }
}

// ---------------- kernel 2: RMSNorm + RoPE + scatter ----------------------
__global__ __launch_bounds__(128) void norm_rope_kernel(
    const float* __restrict__ cosT, const float* __restrict__ sinT,
    const float* __restrict__ nq,  const float* __restrict__ nk,
    const float* __restrict__ naq, const float* __restrict__ nak)
{
    const int s = blockIdx.x, h = blockIdx.y, d = threadIdx.x;
    const float* row = g_qkv + (size_t)s * E3 + h * HDIM;
    float q = row[d];
    float k = row[DIMK + d];
    float v = row[2 * DIMK + d];

    float sq = q * q, sk = k * k;
#pragma unroll
    for (int o = 16; o > 0; o >>= 1) {
        sq += __shfl_xor_sync(0xffffffffu, sq, o);
        sk += __shfl_xor_sync(0xffffffffu, sk, o);
    }
    __shared__ float redq[4], redk[4];
    if ((d & 31) == 0) { redq[d >> 5] = sq; redk[d >> 5] = sk; }
    __syncthreads();
    sq = redq[0] + redq[1] + redq[2] + redq[3];
    sk = redk[0] + redk[1] + redk[2] + redk[3];

    float rq = rsqrtf(sq * (1.0f / HDIM) + EPSV);
    float rk = rsqrtf(sk * (1.0f / HDIM) + EPSV);
    const bool txt = (s < S_TXTC);
    float qn = q * rq * (txt ? naq[d] : nq[d]);
    float kn = k * rk * (txt ? nak[d] : nk[d]);

    __shared__ float qs[128], ksh[128];
    qs[d] = qn; ksh[d] = kn;
    __syncthreads();

    const int i = d >> 1;
    float c  = cosT[s * 64 + i];
    float sn = sinT[s * 64 + i];
    float qo, ko;
    if (d & 1) { qo = qn * c + qs[d - 1] * sn;  ko = kn * c + ksh[d - 1] * sn; }
    else       { qo = qn * c - qs[d + 1] * sn;  ko = kn * c - ksh[d + 1] * sn; }

    size_t o = ((size_t)h * S_TOT + s) * HDIM + d;
    g_Q[o] = qo * QSCALE;
    g_K[o] = ko;
    g_V[o] = v;
}

// ---------------- kernel 3: flash attention (fp32, 64q x 64k tiles) -------
#define DOT4(A, B) ((A).x * (B).x + (A).y * (B).y + (A).z * (B).z + (A).w * (B).w)

__global__ __launch_bounds__(256) void flash_kernel()
{
    extern __shared__ float sm[];
    float* Qs = sm;                 // 64 x 132
    float* Ks = sm + 64 * 132;      // 64 x 132
    float* Vs = sm + 2 * 64 * 132;  // 64 x 132
    float* Ps = sm + 3 * 64 * 132;  // 64 x 68

    const int qt = blockIdx.x, h = blockIdx.y;
    const int t = threadIdx.x, tx = t & 15, ty = t >> 4;

    const float* Qg = g_Q + ((size_t)h * S_TOT + qt * 64) * HDIM;
    for (int i = t; i < 64 * 32; i += 256) {
        int r = i >> 5, c = (i & 31) << 2;
        *(float4*)&Qs[r * 132 + c] = *(const float4*)&Qg[(size_t)r * HDIM + c];
    }

    float m[4], l[4], o[4][8];
#pragma unroll
    for (int i = 0; i < 4; i++) {
        m[i] = -1e30f; l[i] = 0.f;
#pragma unroll
        for (int j = 0; j < 8; j++) o[i][j] = 0.f;
    }

    for (int kt = 0; kt < S_TOT / 64; kt++) {
        const float* Kg = g_K + ((size_t)h * S_TOT + kt * 64) * HDIM;
        const float* Vg = g_V + ((size_t)h * S_TOT + kt * 64) * HDIM;
        for (int i = t; i < 64 * 32; i += 256) {
            int r = i >> 5, c = (i & 31) << 2;
            *(float4*)&Ks[r * 132 + c] = *(const float4*)&Kg[(size_t)r * HDIM + c];
            *(float4*)&Vs[r * 132 + c] = *(const float4*)&Vg[(size_t)r * HDIM + c];
        }
        __syncthreads();

        float sf[4][4];
#pragma unroll
        for (int i = 0; i < 4; i++)
#pragma unroll
            for (int j = 0; j < 4; j++) sf[i][j] = 0.f;

#pragma unroll 4
        for (int dc = 0; dc < HDIM; dc += 4) {
            float4 a[4], b[4];
#pragma unroll
            for (int i = 0; i < 4; i++) a[i] = *(float4*)&Qs[(ty * 4 + i) * 132 + dc];
#pragma unroll
            for (int j = 0; j < 4; j++) b[j] = *(float4*)&Ks[(tx * 4 + j) * 132 + dc];
#pragma unroll
            for (int i = 0; i < 4; i++)
#pragma unroll
                for (int j = 0; j < 4; j++) sf[i][j] += DOT4(a[i], b[j]);
        }

        // online softmax update (rows replicated across the 16 tx threads)
#pragma unroll
        for (int i = 0; i < 4; i++) {
            float mx = fmaxf(fmaxf(sf[i][0], sf[i][1]), fmaxf(sf[i][2], sf[i][3]));
#pragma unroll
            for (int msk = 1; msk < 16; msk <<= 1)
                mx = fmaxf(mx, __shfl_xor_sync(0xffffffffu, mx, msk));
            float mn = fmaxf(m[i], mx);
            float alpha = __expf(m[i] - mn);
            float rs = 0.f;
#pragma unroll
            for (int j = 0; j < 4; j++) { sf[i][j] = __expf(sf[i][j] - mn); rs += sf[i][j]; }
#pragma unroll
            for (int msk = 1; msk < 16; msk <<= 1)
                rs += __shfl_xor_sync(0xffffffffu, rs, msk);
            l[i] = l[i] * alpha + rs;
            m[i] = mn;
#pragma unroll
            for (int j = 0; j < 8; j++) o[i][j] *= alpha;
            *(float4*)&Ps[(ty * 4 + i) * 68 + tx * 4] =
                make_float4(sf[i][0], sf[i][1], sf[i][2], sf[i][3]);
        }
        __syncthreads();

#pragma unroll 2
        for (int kk = 0; kk < 64; kk++) {
            float4 vA = *(float4*)&Vs[kk * 132 + tx * 4];
            float4 vB = *(float4*)&Vs[kk * 132 + 64 + tx * 4];
#pragma unroll
            for (int i = 0; i < 4; i++) {
                float p = Ps[(ty * 4 + i) * 68 + kk];
                o[i][0] = fmaf(p, vA.x, o[i][0]);
                o[i][1] = fmaf(p, vA.y, o[i][1]);
                o[i][2] = fmaf(p, vA.z, o[i][2]);
                o[i][3] = fmaf(p, vA.w, o[i][3]);
                o[i][4] = fmaf(p, vB.x, o[i][4]);
                o[i][5] = fmaf(p, vB.y, o[i][5]);
                o[i][6] = fmaf(p, vB.z, o[i][6]);
                o[i][7] = fmaf(p, vB.w, o[i][7]);
            }
        }
        __syncthreads();
    }

#pragma unroll
    for (int i = 0; i < 4; i++) {
        int s = qt * 64 + ty * 4 + i;
        float inv = 1.0f / l[i];
        float* dst = g_O + (size_t)s * DIMK + h * HDIM;
        float4 w0 = make_float4(o[i][0] * inv, o[i][1] * inv, o[i][2] * inv, o[i][3] * inv);
        float4 w1 = make_float4(o[i][4] * inv, o[i][5] * inv, o[i][6] * inv, o[i][7] * inv);
        *(float4*)&dst[tx * 4] = w0;
        *(float4*)&dst[64 + tx * 4] = w1;
    }
}

// ---------------- kernel 4: output projections + scatter ------------------
__global__ __launch_bounds__(256) void gemm_out_kernel(
    const float* __restrict__ w_img, const float* __restrict__ b_img,
    const float* __restrict__ w_txt, const float* __restrict__ b_txt,
    float* __restrict__ out)
{
    __shared__ float As[16 * 128];
    __shared__ float Bs[16 * 128];
    const int m0 = blockIdx.y * 128;
    const int n0 = blockIdx.x * 128;
    const bool txt = (m0 < S_TXTC);
    const float* A    = g_O + (size_t)m0 * DIMK;
    const float* W    = (txt ? w_txt : w_img) + (size_t)n0 * DIMK;
    const float* bias = (txt ? b_txt : b_img) + n0;

    const int t = threadIdx.x;
    const int tx = t & 15, ty = t >> 4;
    float acc[8][8];
#pragma unroll
    for (int i = 0; i < 8; i++)
#pragma unroll
        for (int j = 0; j < 8; j++) acc[i][j] = 0.f;

    sgemm_main(A, W, acc, As, Bs, t);

#pragma unroll
    for (int i = 0; i < 8; i++) {
        int rloc = (i < 4) ? (ty * 4 + i) : (64 + ty * 4 + i - 4);
        int s = m0 + rloc;
        int orow = txt ? (S_IMGC + s) : (s - S_TXTC);  // out = [img_out ; txt_out]
        float* Crow = out + (size_t)orow * DIMK + n0;
#pragma unroll
        for (int half = 0; half < 2; half++) {
            int cb = half * 64 + tx * 4;
            float4 v;
            v.x = acc[i][half * 4 + 0] + bias[cb + 0];
            v.y = acc[i][half * 4 + 1] + bias[cb + 1];
            v.z = acc[i][half * 4 + 2] + bias[cb + 2];
            v.w = acc[i][half * 4 + 3] + bias[cb + 3];
            *(float4*)(Crow + cb) = v;
        }
    }
}

// ---------------- launch ---------------------------------------------------
extern "C" void kernel_launch(void* const* d_in, const int* in_sizes, int n_in,
                              void* d_out, int out_size)
{
    const float* hid       = (const float*)d_in[0];
    const float* enc       = (const float*)d_in[1];
    const float* cosT      = (const float*)d_in[2];
    const float* sinT      = (const float*)d_in[3];
    const float* w_qkv     = (const float*)d_in[4];
    const float* b_qkv     = (const float*)d_in[5];
    const float* w_add     = (const float*)d_in[6];
    const float* b_add     = (const float*)d_in[7];
    const float* nq        = (const float*)d_in[8];
    const float* nk        = (const float*)d_in[9];
    const float* naq       = (const float*)d_in[10];
    const float* nak       = (const float*)d_in[11];
    const float* w_out     = (const float*)d_in[12];
    const float* b_out     = (const float*)d_in[13];
    const float* w_add_out = (const float*)d_in[14];
    const float* b_add_out = (const float*)d_in[15];
    float* out = (float*)d_out;

    // 1. QKV projection for both streams (txt rows 0..511, img rows 512..2559)
    gemm_qkv_kernel<<<dim3(E3 / 128, S_TOT / 128), 256>>>(
        hid, enc, w_qkv, b_qkv, w_add, b_add);

    // 2. RMSNorm + RoPE + layout scatter
    norm_rope_kernel<<<dim3(S_TOT, NHEADS), 128>>>(cosT, sinT, nq, nk, naq, nak);

    // 3. Flash attention
    const int smem_flash = (3 * 64 * 132 + 64 * 68) * (int)sizeof(float);  // 118,784 B
    cudaFuncSetAttribute(flash_kernel,
                         cudaFuncAttributeMaxDynamicSharedMemorySize, smem_flash);
    flash_kernel<<<dim3(S_TOT / 64, NHEADS), 256, smem_flash>>>();

    // 4. Output projections (img -> w_out/b_out, txt -> w_add_out/b_add_out)
    gemm_out_kernel<<<dim3(DIMK / 128, S_TOT / 128), 256>>>(
        w_out, b_out, w_add_out, b_add_out, out);
}

// round 2
// speedup vs baseline: 3.5218x; 3.5218x over previous
#include <cuda_runtime.h>
#include <cstdint>

#define S_TOT  2560
#define S_TXTC 512
#define S_IMGC 2048
#define DIMK   3072
#define NHEADS 24
#define HDIM   128
#define E3     9216
#define EPSV   1e-6f
#define QSCALE 0.088388347648318447f   // 1/sqrt(128)

// ---------------- scratch (device globals; no allocation allowed) ----------
static __device__ float g_qkv[S_TOT * E3];
static __device__ float g_Q[NHEADS * S_TOT * HDIM];   // [h][s][d], pre-scaled 1/sqrt(D)
static __device__ float g_K[NHEADS * S_TOT * HDIM];
static __device__ float g_V[NHEADS * S_TOT * HDIM];
static __device__ float g_O[S_TOT * DIMK];            // attention out [s][h*D+d]

// ---------------- tf32 helpers ---------------------------------------------
__device__ __forceinline__ unsigned f2tf(float x) {
    unsigned u;
    asm("cvt.rna.tf32.f32 %0, %1;" : "=r"(u) : "f"(x));
    return u;
}

__device__ __forceinline__ void mma8(float (&d)[4], const unsigned (&a)[4],
                                     const unsigned (&b)[2]) {
    asm volatile(
        "mma.sync.aligned.m16n8k8.row.col.f32.tf32.tf32.f32 "
        "{%0,%1,%2,%3}, {%4,%5,%6,%7}, {%8,%9}, {%0,%1,%2,%3};\n"
        : "+f"(d[0]), "+f"(d[1]), "+f"(d[2]), "+f"(d[3])
        : "r"(a[0]), "r"(a[1]), "r"(a[2]), "r"(a[3]), "r"(b[0]), "r"(b[1]));
}

// ---------------- 128x128 tf32 GEMM mainloop (NT, K=3072, BK=32, dbl-buf) --
// acc[mt][nt][c]: warp (wm,wn) owns rows wm*64+mt*16, cols wn*32+nt*8
#define SSTAGE (128 * 36)

__device__ __forceinline__ void gemm_tf32_main(
    const float* __restrict__ A, const float* __restrict__ W,
    unsigned* sA, unsigned* sB, float (&acc)[4][4][4], int t)
{
    const int lane = t & 31, wid = t >> 5;
    const int g = lane >> 2, t4 = lane & 3;
    const int wm = wid >> 2, wn = wid & 3;
    const int lr = t >> 3;             // base load row (0..31), +32 per l
    const int lc = (t & 7) << 2;       // load col (float offset, 0..28)

    float4 ra[4], rb[4];
#pragma unroll
    for (int l = 0; l < 4; l++) {
        int r = lr + l * 32;
        ra[l] = *(const float4*)(A + (size_t)r * DIMK + lc);
        rb[l] = *(const float4*)(W + (size_t)r * DIMK + lc);
    }
#pragma unroll
    for (int l = 0; l < 4; l++) {
        int bo = (lr + l * 32) * 36 + lc;
        sA[bo + 0] = f2tf(ra[l].x); sA[bo + 1] = f2tf(ra[l].y);
        sA[bo + 2] = f2tf(ra[l].z); sA[bo + 3] = f2tf(ra[l].w);
        sB[bo + 0] = f2tf(rb[l].x); sB[bo + 1] = f2tf(rb[l].y);
        sB[bo + 2] = f2tf(rb[l].z); sB[bo + 3] = f2tf(rb[l].w);
    }
    __syncthreads();

    int cur = 0;
    const int NST = DIMK / 32;   // 96
    for (int s = 0; s < NST; s++) {
        if (s + 1 < NST) {
            int k0 = (s + 1) * 32;
#pragma unroll
            for (int l = 0; l < 4; l++) {
                int r = lr + l * 32;
                ra[l] = *(const float4*)(A + (size_t)r * DIMK + k0 + lc);
                rb[l] = *(const float4*)(W + (size_t)r * DIMK + k0 + lc);
            }
        }
        const unsigned* cA = sA + cur * SSTAGE;
        const unsigned* cB = sB + cur * SSTAGE;
#pragma unroll
        for (int ks = 0; ks < 4; ks++) {
            int k = ks * 8;
            unsigned af[4][4], bf[4][2];
#pragma unroll
            for (int mt = 0; mt < 4; mt++) {
                const unsigned* p = cA + (wm * 64 + mt * 16) * 36 + k;
                af[mt][0] = p[g * 36 + t4];
                af[mt][1] = p[(g + 8) * 36 + t4];
                af[mt][2] = p[g * 36 + t4 + 4];
                af[mt][3] = p[(g + 8) * 36 + t4 + 4];
            }
#pragma unroll
            for (int nt = 0; nt < 4; nt++) {
                const unsigned* p = cB + (wn * 32 + nt * 8 + g) * 36 + k;
                bf[nt][0] = p[t4];
                bf[nt][1] = p[t4 + 4];
            }
#pragma unroll
            for (int mt = 0; mt < 4; mt++)
#pragma unroll
                for (int nt = 0; nt < 4; nt++)
                    mma8(acc[mt][nt], af[mt], bf[nt]);
        }
        if (s + 1 < NST) {
            unsigned* nA = sA + (cur ^ 1) * SSTAGE;
            unsigned* nB = sB + (cur ^ 1) * SSTAGE;
#pragma unroll
            for (int l = 0; l < 4; l++) {
                int bo = (lr + l * 32) * 36 + lc;
                nA[bo + 0] = f2tf(ra[l].x); nA[bo + 1] = f2tf(ra[l].y);
                nA[bo + 2] = f2tf(ra[l].z); nA[bo + 3] = f2tf(ra[l].w);
                nB[bo + 0] = f2tf(rb[l].x); nB[bo + 1] = f2tf(rb[l].y);
                nB[bo + 2] = f2tf(rb[l].z); nB[bo + 3] = f2tf(rb[l].w);
            }
        }
        __syncthreads();
        cur ^= 1;
    }
}

#define GEMM_SMEM_BYTES (4 * SSTAGE * 4)   // 73728

// ---------------- kernel 1: QKV projection ---------------------------------
__global__ __launch_bounds__(256) void gemm_qkv_kernel(
    const float* __restrict__ x_img, const float* __restrict__ x_txt,
    const float* __restrict__ w_img, const float* __restrict__ b_img,
    const float* __restrict__ w_txt, const float* __restrict__ b_txt)
{
    extern __shared__ unsigned gsm[];
    unsigned* sA = gsm;
    unsigned* sB = gsm + 2 * SSTAGE;

    const int m0 = blockIdx.y * 128;
    const int n0 = blockIdx.x * 128;
    const bool txt = (m0 < S_TXTC);
    const float* A    = txt ? (x_txt + (size_t)m0 * DIMK)
                            : (x_img + (size_t)(m0 - S_TXTC) * DIMK);
    const float* W    = (txt ? w_txt : w_img) + (size_t)n0 * DIMK;
    const float* bias = txt ? b_txt : b_img;

    const int t = threadIdx.x;
    float acc[4][4][4];
#pragma unroll
    for (int i = 0; i < 4; i++)
#pragma unroll
        for (int j = 0; j < 4; j++)
#pragma unroll
            for (int c = 0; c < 4; c++) acc[i][j][c] = 0.f;

    gemm_tf32_main(A, W, sA, sB, acc, t);

    const int lane = t & 31, wid = t >> 5;
    const int g = lane >> 2, t4 = lane & 3;
    const int wm = wid >> 2, wn = wid & 3;
#pragma unroll
    for (int mt = 0; mt < 4; mt++) {
        int r0 = m0 + wm * 64 + mt * 16 + g;
#pragma unroll
        for (int nt = 0; nt < 4; nt++) {
            int c = n0 + wn * 32 + nt * 8 + t4 * 2;
            float b0 = bias[c - n0 + wn * 32 * 0 + (c - n0) * 0 + (c - n0)];
            (void)b0;
            float bx = bias[c - n0 + n0 - n0 + (wn * 0)];
            (void)bx;
            float2 v0 = make_float2(acc[mt][nt][0] + bias[c],
                                    acc[mt][nt][1] + bias[c + 1]);
            float2 v1 = make_float2(acc[mt][nt][2] + bias[c],
                                    acc[mt][nt][3] + bias[c + 1]);
            *(float2*)(g_qkv + (size_t)r0 * E3 + c) = v0;
            *(float2*)(g_qkv + (size_t)(r0 + 8) * E3 + c) = v1;
        }
    }
}

// ---------------- kernel 2: RMSNorm + RoPE + scatter ------------------------
__global__ __launch_bounds__(128) void norm_rope_kernel(
    const float* __restrict__ cosT, const float* __restrict__ sinT,
    const float* __restrict__ nq,  const float* __restrict__ nk,
    const float* __restrict__ naq, const float* __restrict__ nak)
{
    const int s = blockIdx.x, h = blockIdx.y, d = threadIdx.x;
    const float* row = g_qkv + (size_t)s * E3 + h * HDIM;
    float q = row[d];
    float k = row[DIMK + d];
    float v = row[2 * DIMK + d];

    float sq = q * q, sk = k * k;
#pragma unroll
    for (int o = 16; o > 0; o >>= 1) {
        sq += __shfl_xor_sync(0xffffffffu, sq, o);
        sk += __shfl_xor_sync(0xffffffffu, sk, o);
    }
    __shared__ float redq[4], redk[4];
    if ((d & 31) == 0) { redq[d >> 5] = sq; redk[d >> 5] = sk; }
    __syncthreads();
    sq = redq[0] + redq[1] + redq[2] + redq[3];
    sk = redk[0] + redk[1] + redk[2] + redk[3];

    float rq = rsqrtf(sq * (1.0f / HDIM) + EPSV);
    float rk = rsqrtf(sk * (1.0f / HDIM) + EPSV);
    const bool txt = (s < S_TXTC);
    float qn = q * rq * (txt ? naq[d] : nq[d]);
    float kn = k * rk * (txt ? nak[d] : nk[d]);

    __shared__ float qs[128], ksh[128];
    qs[d] = qn; ksh[d] = kn;
    __syncthreads();

    const int i = d >> 1;
    float c  = cosT[s * 64 + i];
    float sn = sinT[s * 64 + i];
    float qo, ko;
    if (d & 1) { qo = qn * c + qs[d - 1] * sn;  ko = kn * c + ksh[d - 1] * sn; }
    else       { qo = qn * c - qs[d + 1] * sn;  ko = kn * c - ksh[d + 1] * sn; }

    size_t o = ((size_t)h * S_TOT + s) * HDIM + d;
    g_Q[o] = qo * QSCALE;
    g_K[o] = ko;
    g_V[o] = v;
}

// ---------------- kernel 3: flash attention (tf32 mma) ----------------------
// 4 warps/block, 64 q-rows (16/warp), 64-key tiles, D=128.
#define FLASH_SMEM_BYTES ((3 * 64 * 132 + 64 * 68) * 4)   // 118784

__global__ __launch_bounds__(128) void flash_tf32_kernel()
{
    extern __shared__ unsigned fsm[];
    unsigned* Qs = fsm;                 // [64][132]  (q, d)
    unsigned* Ks = fsm + 64 * 132;      // [64][132]  (key, d)
    unsigned* Vs = fsm + 2 * 64 * 132;  // [64][132]  (key, d)
    unsigned* Ps = fsm + 3 * 64 * 132;  // [64][68]   (q, key) tf32

    const int qt = blockIdx.x, h = blockIdx.y;
    const int t = threadIdx.x, lane = t & 31, wid = t >> 5;
    const int g = lane >> 2, t4 = lane & 3;
    const int qb = wid * 16;

    const float* Qg = g_Q + ((size_t)h * S_TOT + qt * 64) * HDIM;
#pragma unroll
    for (int l = 0; l < 16; l++) {
        int idx = t + l * 128;
        int r = idx >> 5, c = (idx & 31) << 2;
        float4 v = *(const float4*)(Qg + (size_t)r * HDIM + c);
        int bo = r * 132 + c;
        Qs[bo + 0] = f2tf(v.x); Qs[bo + 1] = f2tf(v.y);
        Qs[bo + 2] = f2tf(v.z); Qs[bo + 3] = f2tf(v.w);
    }

    float mrow[2] = {-1e30f, -1e30f}, lrow[2] = {0.f, 0.f};
    float o[16][4];
#pragma unroll
    for (int dt = 0; dt < 16; dt++)
#pragma unroll
        for (int c = 0; c < 4; c++) o[dt][c] = 0.f;

    const float* Kg0 = g_K + (size_t)h * S_TOT * HDIM;
    const float* Vg0 = g_V + (size_t)h * S_TOT * HDIM;

    for (int kt = 0; kt < S_TOT / 64; kt++) {
        __syncthreads();   // previous PV done before overwriting tiles
        const float* Kg = Kg0 + (size_t)kt * 64 * HDIM;
        const float* Vg = Vg0 + (size_t)kt * 64 * HDIM;
#pragma unroll
        for (int l = 0; l < 16; l++) {
            int idx = t + l * 128;
            int r = idx >> 5, c = (idx & 31) << 2;
            int bo = r * 132 + c;
            float4 kv = *(const float4*)(Kg + (size_t)r * HDIM + c);
            Ks[bo + 0] = f2tf(kv.x); Ks[bo + 1] = f2tf(kv.y);
            Ks[bo + 2] = f2tf(kv.z); Ks[bo + 3] = f2tf(kv.w);
            float4 vv = *(const float4*)(Vg + (size_t)r * HDIM + c);
            Vs[bo + 0] = f2tf(vv.x); Vs[bo + 1] = f2tf(vv.y);
            Vs[bo + 2] = f2tf(vv.z); Vs[bo + 3] = f2tf(vv.w);
        }
        __syncthreads();

        // S = Q K^T  (scores in fragments: 8 n-tiles of 8 keys)
        float sc[8][4];
#pragma unroll
        for (int nt = 0; nt < 8; nt++)
#pragma unroll
            for (int c = 0; c < 4; c++) sc[nt][c] = 0.f;

#pragma unroll
        for (int ks = 0; ks < 16; ks++) {
            int k = ks * 8;
            unsigned af[4];
            af[0] = Qs[(qb + g) * 132 + k + t4];
            af[1] = Qs[(qb + g + 8) * 132 + k + t4];
            af[2] = Qs[(qb + g) * 132 + k + t4 + 4];
            af[3] = Qs[(qb + g + 8) * 132 + k + t4 + 4];
#pragma unroll
            for (int nt = 0; nt < 8; nt++) {
                unsigned bf[2];
                bf[0] = Ks[(nt * 8 + g) * 132 + k + t4];
                bf[1] = Ks[(nt * 8 + g) * 132 + k + t4 + 4];
                mma8(sc[nt], af, bf);
            }
        }

        // online softmax: thread owns rows (qb+g) [c0,c1] and (qb+g+8) [c2,c3]
        float mx0 = -1e30f, mx1 = -1e30f;
#pragma unroll
        for (int nt = 0; nt < 8; nt++) {
            mx0 = fmaxf(mx0, fmaxf(sc[nt][0], sc[nt][1]));
            mx1 = fmaxf(mx1, fmaxf(sc[nt][2], sc[nt][3]));
        }
        mx0 = fmaxf(mx0, __shfl_xor_sync(0xffffffffu, mx0, 1));
        mx0 = fmaxf(mx0, __shfl_xor_sync(0xffffffffu, mx0, 2));
        mx1 = fmaxf(mx1, __shfl_xor_sync(0xffffffffu, mx1, 1));
        mx1 = fmaxf(mx1, __shfl_xor_sync(0xffffffffu, mx1, 2));
        float m0n = fmaxf(mrow[0], mx0), m1n = fmaxf(mrow[1], mx1);
        float a0 = __expf(mrow[0] - m0n), a1 = __expf(mrow[1] - m1n);
        mrow[0] = m0n; mrow[1] = m1n;

        float rs0 = 0.f, rs1 = 0.f;
#pragma unroll
        for (int nt = 0; nt < 8; nt++) {
            sc[nt][0] = __expf(sc[nt][0] - m0n);
            sc[nt][1] = __expf(sc[nt][1] - m0n);
            sc[nt][2] = __expf(sc[nt][2] - m1n);
            sc[nt][3] = __expf(sc[nt][3] - m1n);
            rs0 += sc[nt][0] + sc[nt][1];
            rs1 += sc[nt][2] + sc[nt][3];
        }
        rs0 += __shfl_xor_sync(0xffffffffu, rs0, 1);
        rs0 += __shfl_xor_sync(0xffffffffu, rs0, 2);
        rs1 += __shfl_xor_sync(0xffffffffu, rs1, 1);
        rs1 += __shfl_xor_sync(0xffffffffu, rs1, 2);
        lrow[0] = lrow[0] * a0 + rs0;
        lrow[1] = lrow[1] * a1 + rs1;

#pragma unroll
        for (int dt = 0; dt < 16; dt++) {
            o[dt][0] *= a0; o[dt][1] *= a0;
            o[dt][2] *= a1; o[dt][3] *= a1;
        }

#pragma unroll
        for (int nt = 0; nt < 8; nt++) {
            int pb = (qb + g) * 68 + nt * 8 + t4 * 2;
            Ps[pb]     = f2tf(sc[nt][0]);
            Ps[pb + 1] = f2tf(sc[nt][1]);
            Ps[pb + 8 * 68]     = f2tf(sc[nt][2]);
            Ps[pb + 8 * 68 + 1] = f2tf(sc[nt][3]);
        }
        __syncwarp();

        // O += P V  (P row-major A-frag from Ps; V B-frag via transposed index)
#pragma unroll
        for (int ks = 0; ks < 8; ks++) {
            int k = ks * 8;
            unsigned pa[4];
            pa[0] = Ps[(qb + g) * 68 + k + t4];
            pa[1] = Ps[(qb + g + 8) * 68 + k + t4];
            pa[2] = Ps[(qb + g) * 68 + k + t4 + 4];
            pa[3] = Ps[(qb + g + 8) * 68 + k + t4 + 4];
#pragma unroll
            for (int dt = 0; dt < 16; dt++) {
                unsigned bf[2];
                bf[0] = Vs[(k + t4) * 132 + dt * 8 + g];
                bf[1] = Vs[(k + t4 + 4) * 132 + dt * 8 + g];
                mma8(o[dt], pa, bf);
            }
        }
    }

    float inv0 = 1.0f / lrow[0], inv1 = 1.0f / lrow[1];
    int s0 = qt * 64 + qb + g;
    float* dst0 = g_O + (size_t)s0 * DIMK + h * HDIM;
    float* dst1 = dst0 + (size_t)8 * DIMK;
#pragma unroll
    for (int dt = 0; dt < 16; dt++) {
        int d = dt * 8 + t4 * 2;
        *(float2*)(dst0 + d) = make_float2(o[dt][0] * inv0, o[dt][1] * inv0);
        *(float2*)(dst1 + d) = make_float2(o[dt][2] * inv1, o[dt][3] * inv1);
    }
}

// ---------------- kernel 4: output projections + scatter --------------------
__global__ __launch_bounds__(256) void gemm_out_kernel(
    const float* __restrict__ w_img, const float* __restrict__ b_img,
    const float* __restrict__ w_txt, const float* __restrict__ b_txt,
    float* __restrict__ out)
{
    extern __shared__ unsigned gsm[];
    unsigned* sA = gsm;
    unsigned* sB = gsm + 2 * SSTAGE;

    const int m0 = blockIdx.y * 128;
    const int n0 = blockIdx.x * 128;
    const bool txt = (m0 < S_TXTC);
    const float* A    = g_O + (size_t)m0 * DIMK;
    const float* W    = (txt ? w_txt : w_img) + (size_t)n0 * DIMK;
    const float* bias = txt ? b_txt : b_img;

    const int t = threadIdx.x;
    float acc[4][4][4];
#pragma unroll
    for (int i = 0; i < 4; i++)
#pragma unroll
        for (int j = 0; j < 4; j++)
#pragma unroll
            for (int c = 0; c < 4; c++) acc[i][j][c] = 0.f;

    gemm_tf32_main(A, W, sA, sB, acc, t);

    const int lane = t & 31, wid = t >> 5;
    const int g = lane >> 2, t4 = lane & 3;
    const int wm = wid >> 2, wn = wid & 3;
#pragma unroll
    for (int mt = 0; mt < 4; mt++) {
        int s = m0 + wm * 64 + mt * 16 + g;
        int orow0 = txt ? (S_IMGC + s) : (s - S_TXTC);
        int orow1 = orow0 + 8;
#pragma unroll
        for (int nt = 0; nt < 4; nt++) {
            int c = n0 + wn * 32 + nt * 8 + t4 * 2;
            float2 v0 = make_float2(acc[mt][nt][0] + bias[c],
                                    acc[mt][nt][1] + bias[c + 1]);
            float2 v1 = make_float2(acc[mt][nt][2] + bias[c],
                                    acc[mt][nt][3] + bias[c + 1]);
            *(float2*)(out + (size_t)orow0 * DIMK + c) = v0;
            *(float2*)(out + (size_t)orow1 * DIMK + c) = v1;
        }
    }
}

// ---------------- launch ----------------------------------------------------
extern "C" void kernel_launch(void* const* d_in, const int* in_sizes, int n_in,
                              void* d_out, int out_size)
{
    const float* hid       = (const float*)d_in[0];
    const float* enc       = (const float*)d_in[1];
    const float* cosT      = (const float*)d_in[2];
    const float* sinT      = (const float*)d_in[3];
    const float* w_qkv     = (const float*)d_in[4];
    const float* b_qkv     = (const float*)d_in[5];
    const float* w_add     = (const float*)d_in[6];
    const float* b_add     = (const float*)d_in[7];
    const float* nq        = (const float*)d_in[8];
    const float* nk        = (const float*)d_in[9];
    const float* naq       = (const float*)d_in[10];
    const float* nak       = (const float*)d_in[11];
    const float* w_out     = (const float*)d_in[12];
    const float* b_out     = (const float*)d_in[13];
    const float* w_add_out = (const float*)d_in[14];
    const float* b_add_out = (const float*)d_in[15];
    float* out = (float*)d_out;

    static bool attr_done = false;
    if (!attr_done) {
        cudaFuncSetAttribute(gemm_qkv_kernel,
            cudaFuncAttributeMaxDynamicSharedMemorySize, GEMM_SMEM_BYTES);
        cudaFuncSetAttribute(gemm_out_kernel,
            cudaFuncAttributeMaxDynamicSharedMemorySize, GEMM_SMEM_BYTES);
        cudaFuncSetAttribute(flash_tf32_kernel,
            cudaFuncAttributeMaxDynamicSharedMemorySize, FLASH_SMEM_BYTES);
        attr_done = true;
    }

    gemm_qkv_kernel<<<dim3(E3 / 128, S_TOT / 128), 256, GEMM_SMEM_BYTES>>>(
        hid, enc, w_qkv, b_qkv, w_add, b_add);

    norm_rope_kernel<<<dim3(S_TOT, NHEADS), 128>>>(cosT, sinT, nq, nk, naq, nak);

    flash_tf32_kernel<<<dim3(S_TOT / 64, NHEADS), 128, FLASH_SMEM_BYTES>>>();

    gemm_out_kernel<<<dim3(DIMK / 128, S_TOT / 128), 256, GEMM_SMEM_BYTES>>>(
        w_out, b_out, w_add_out, b_add_out, out);
}

// round 4
// speedup vs baseline: 4.0525x; 1.1507x over previous
#include <cuda_runtime.h>
#include <cstdint>

#define S_TOT  2560
#define S_TXTC 512
#define S_IMGC 2048
#define DIMK   3072
#define NHEADS 24
#define HDIM   128
#define E3     9216
#define EPSV   1e-6f
#define QSCALE 0.088388347648318447f   // 1/sqrt(128)

// ---------------- scratch ---------------------------------------------------
static __device__ float g_qkv[S_TOT * E3];
static __device__ float g_Q[NHEADS * S_TOT * HDIM];
static __device__ float g_K[NHEADS * S_TOT * HDIM];
static __device__ float g_V[NHEADS * S_TOT * HDIM];
static __device__ float g_O[S_TOT * DIMK];

// ---------------- helpers ---------------------------------------------------
__device__ __forceinline__ unsigned f2tf(float x) {
    unsigned u;
    asm("cvt.rna.tf32.f32 %0, %1;" : "=r"(u) : "f"(x));
    return u;
}
__device__ __forceinline__ uint32_t smem_u32(const void* p) {
    uint32_t a;
    asm("{ .reg .u64 t; cvta.to.shared.u64 t, %1; cvt.u32.u64 %0, t; }"
        : "=r"(a) : "l"(p));
    return a;
}
__device__ __forceinline__ void mma8(float (&d)[4], const unsigned (&a)[4],
                                     const unsigned (&b)[2]) {
    asm volatile(
        "mma.sync.aligned.m16n8k8.row.col.f32.tf32.tf32.f32 "
        "{%0,%1,%2,%3}, {%4,%5,%6,%7}, {%8,%9}, {%0,%1,%2,%3};\n"
        : "+f"(d[0]), "+f"(d[1]), "+f"(d[2]), "+f"(d[3])
        : "r"(a[0]), "r"(a[1]), "r"(a[2]), "r"(a[3]), "r"(b[0]), "r"(b[1]));
}
#define LDSM4(r0, r1, r2, r3, addr)                                            \
    asm volatile("ldmatrix.sync.aligned.m8n8.x4.shared.b16 {%0,%1,%2,%3}, [%4];" \
                 : "=r"(r0), "=r"(r1), "=r"(r2), "=r"(r3) : "r"(addr))
#define STS128(addr, x, y, z, w)                                               \
    asm volatile("st.shared.v4.b32 [%0], {%1,%2,%3,%4};"                       \
                 :: "r"(addr), "r"(x), "r"(y), "r"(z), "r"(w) : "memory")
#define STS32(addr, x)                                                         \
    asm volatile("st.shared.b32 [%0], %1;" :: "r"(addr), "r"(x) : "memory")

// ======================= GEMM: 128x128, BK=32, dbl-buffered =================
// smem: stage layout (words): A0 [0,4608) A1 [4608,9216) B0 [9216,..) B1 ...
// A/B stage: 128 rows x 36 words (32 data + 4 pad), row-major.
#define SROW 36
#define STAGE_W (128 * SROW)
#define STAGE_B (STAGE_W * 4)                 // 18432
#define GEMM_SMEM_BYTES (4 * STAGE_B)         // 73728

__device__ __forceinline__ void gemm_tf32_main(
    const float* __restrict__ A, const float* __restrict__ W,
    uint32_t su, float (&acc)[4][4][4], int t)
{
    const int lane = t & 31, wid = t >> 5;
    const int wm = wid >> 2, wn = wid & 3;
    const int lr = t >> 3;               // load row 0..31 (+32 per l)
    const int lc = (t & 7) << 2;         // load col 0..28

    // ldmatrix base addresses (stage 0; add stage/tile offsets at use)
    const int arow = (lane & 7) + ((lane >> 3) & 1) * 8;
    const int acol = (lane >> 4) * 4;
    const int brow = (lane & 7) + ((lane >> 4) & 1) * 8;
    const int bcol = ((lane >> 3) & 1) * 4;
    const uint32_t aA0 = su + (uint32_t)((wm * 64 + arow) * SROW + acol) * 4;
    const uint32_t aB0 = su + 2 * STAGE_B +
                         (uint32_t)((wn * 32 + brow) * SROW + bcol) * 4;

    float4 ra[4], rb[4];
#pragma unroll
    for (int l = 0; l < 4; l++) {
        int r = lr + l * 32;
        ra[l] = *(const float4*)(A + (size_t)r * DIMK + lc);
        rb[l] = *(const float4*)(W + (size_t)r * DIMK + lc);
    }
#pragma unroll
    for (int l = 0; l < 4; l++) {
        uint32_t o = (uint32_t)((lr + l * 32) * SROW + lc) * 4;
        STS128(su + o, f2tf(ra[l].x), f2tf(ra[l].y), f2tf(ra[l].z), f2tf(ra[l].w));
        STS128(su + 2 * STAGE_B + o,
               f2tf(rb[l].x), f2tf(rb[l].y), f2tf(rb[l].z), f2tf(rb[l].w));
    }
    __syncthreads();

    int cur = 0;
    const int NST = DIMK / 32;   // 96
    for (int s = 0; s < NST; s++) {
        if (s + 1 < NST) {
            int k0 = (s + 1) * 32;
#pragma unroll
            for (int l = 0; l < 4; l++) {
                int r = lr + l * 32;
                ra[l] = *(const float4*)(A + (size_t)r * DIMK + k0 + lc);
                rb[l] = *(const float4*)(W + (size_t)r * DIMK + k0 + lc);
            }
        }
        const uint32_t cA = aA0 + cur * STAGE_B;
        const uint32_t cB = aB0 + cur * STAGE_B;
#pragma unroll
        for (int ks = 0; ks < 4; ks++) {
            unsigned af[4][4], bf[4][2];
#pragma unroll
            for (int mt = 0; mt < 4; mt++)
                LDSM4(af[mt][0], af[mt][1], af[mt][2], af[mt][3],
                      cA + mt * (16 * SROW * 4) + ks * 32);
            LDSM4(bf[0][0], bf[0][1], bf[1][0], bf[1][1], cB + ks * 32);
            LDSM4(bf[2][0], bf[2][1], bf[3][0], bf[3][1],
                  cB + 16 * SROW * 4 + ks * 32);
#pragma unroll
            for (int mt = 0; mt < 4; mt++)
#pragma unroll
                for (int nt = 0; nt < 4; nt++)
                    mma8(acc[mt][nt], af[mt], bf[nt]);
        }
        if (s + 1 < NST) {
            const uint32_t nx = (cur ^ 1) * STAGE_B;
#pragma unroll
            for (int l = 0; l < 4; l++) {
                uint32_t o = (uint32_t)((lr + l * 32) * SROW + lc) * 4;
                STS128(su + nx + o,
                       f2tf(ra[l].x), f2tf(ra[l].y), f2tf(ra[l].z), f2tf(ra[l].w));
                STS128(su + 2 * STAGE_B + nx + o,
                       f2tf(rb[l].x), f2tf(rb[l].y), f2tf(rb[l].z), f2tf(rb[l].w));
            }
        }
        __syncthreads();
        cur ^= 1;
    }
}

// ---------------- kernel 1: QKV projection ----------------------------------
__global__ __launch_bounds__(256, 2) void gemm_qkv_kernel(
    const float* __restrict__ x_img, const float* __restrict__ x_txt,
    const float* __restrict__ w_img, const float* __restrict__ b_img,
    const float* __restrict__ w_txt, const float* __restrict__ b_txt)
{
    extern __shared__ unsigned gsm[];
    const uint32_t su = smem_u32(gsm);
    const int m0 = blockIdx.y * 128;
    const int n0 = blockIdx.x * 128;
    const bool txt = (m0 < S_TXTC);
    const float* A    = txt ? (x_txt + (size_t)m0 * DIMK)
                            : (x_img + (size_t)(m0 - S_TXTC) * DIMK);
    const float* W    = (txt ? w_txt : w_img) + (size_t)n0 * DIMK;
    const float* bias = txt ? b_txt : b_img;

    const int t = threadIdx.x;
    float acc[4][4][4];
#pragma unroll
    for (int i = 0; i < 4; i++)
#pragma unroll
        for (int j = 0; j < 4; j++)
#pragma unroll
            for (int c = 0; c < 4; c++) acc[i][j][c] = 0.f;

    gemm_tf32_main(A, W, su, acc, t);

    const int lane = t & 31, wid = t >> 5;
    const int g = lane >> 2, t4 = lane & 3;
    const int wm = wid >> 2, wn = wid & 3;
#pragma unroll
    for (int mt = 0; mt < 4; mt++) {
        int r0 = m0 + wm * 64 + mt * 16 + g;
#pragma unroll
        for (int nt = 0; nt < 4; nt++) {
            int c = n0 + wn * 32 + nt * 8 + t4 * 2;
            float2 v0 = make_float2(acc[mt][nt][0] + bias[c],
                                    acc[mt][nt][1] + bias[c + 1]);
            float2 v1 = make_float2(acc[mt][nt][2] + bias[c],
                                    acc[mt][nt][3] + bias[c + 1]);
            *(float2*)(g_qkv + (size_t)r0 * E3 + c) = v0;
            *(float2*)(g_qkv + (size_t)(r0 + 8) * E3 + c) = v1;
        }
    }
}

// ---------------- kernel 4: output projections + scatter --------------------
__global__ __launch_bounds__(256, 2) void gemm_out_kernel(
    const float* __restrict__ w_img, const float* __restrict__ b_img,
    const float* __restrict__ w_txt, const float* __restrict__ b_txt,
    float* __restrict__ out)
{
    extern __shared__ unsigned gsm[];
    const uint32_t su = smem_u32(gsm);
    const int m0 = blockIdx.y * 128;
    const int n0 = blockIdx.x * 128;
    const bool txt = (m0 < S_TXTC);
    const float* A    = g_O + (size_t)m0 * DIMK;
    const float* W    = (txt ? w_txt : w_img) + (size_t)n0 * DIMK;
    const float* bias = txt ? b_txt : b_img;

    const int t = threadIdx.x;
    float acc[4][4][4];
#pragma unroll
    for (int i = 0; i < 4; i++)
#pragma unroll
        for (int j = 0; j < 4; j++)
#pragma unroll
            for (int c = 0; c < 4; c++) acc[i][j][c] = 0.f;

    gemm_tf32_main(A, W, su, acc, t);

    const int lane = t & 31, wid = t >> 5;
    const int g = lane >> 2, t4 = lane & 3;
    const int wm = wid >> 2, wn = wid & 3;
#pragma unroll
    for (int mt = 0; mt < 4; mt++) {
        int s = m0 + wm * 64 + mt * 16 + g;
        int orow0 = txt ? (S_IMGC + s) : (s - S_TXTC);
        int orow1 = orow0 + 8;
#pragma unroll
        for (int nt = 0; nt < 4; nt++) {
            int c = n0 + wn * 32 + nt * 8 + t4 * 2;
            float2 v0 = make_float2(acc[mt][nt][0] + bias[c],
                                    acc[mt][nt][1] + bias[c + 1]);
            float2 v1 = make_float2(acc[mt][nt][2] + bias[c],
                                    acc[mt][nt][3] + bias[c + 1]);
            *(float2*)(out + (size_t)orow0 * DIMK + c) = v0;
            *(float2*)(out + (size_t)orow1 * DIMK + c) = v1;
        }
    }
}

// ---------------- kernel 2: RMSNorm + RoPE + scatter ------------------------
__global__ __launch_bounds__(128) void norm_rope_kernel(
    const float* __restrict__ cosT, const float* __restrict__ sinT,
    const float* __restrict__ nq,  const float* __restrict__ nk,
    const float* __restrict__ naq, const float* __restrict__ nak)
{
    const int s = blockIdx.x, h = blockIdx.y, d = threadIdx.x;
    const float* row = g_qkv + (size_t)s * E3 + h * HDIM;
    float q = row[d];
    float k = row[DIMK + d];
    float v = row[2 * DIMK + d];

    float sq = q * q, sk = k * k;
#pragma unroll
    for (int o = 16; o > 0; o >>= 1) {
        sq += __shfl_xor_sync(0xffffffffu, sq, o);
        sk += __shfl_xor_sync(0xffffffffu, sk, o);
    }
    __shared__ float redq[4], redk[4];
    if ((d & 31) == 0) { redq[d >> 5] = sq; redk[d >> 5] = sk; }
    __syncthreads();
    sq = redq[0] + redq[1] + redq[2] + redq[3];
    sk = redk[0] + redk[1] + redk[2] + redk[3];

    float rq = rsqrtf(sq * (1.0f / HDIM) + EPSV);
    float rk = rsqrtf(sk * (1.0f / HDIM) + EPSV);
    const bool txt = (s < S_TXTC);
    float qn = q * rq * (txt ? naq[d] : nq[d]);
    float kn = k * rk * (txt ? nak[d] : nk[d]);

    __shared__ float qs[128], ksh[128];
    qs[d] = qn; ksh[d] = kn;
    __syncthreads();

    const int i = d >> 1;
    float c  = cosT[s * 64 + i];
    float sn = sinT[s * 64 + i];
    float qo, ko;
    if (d & 1) { qo = qn * c + qs[d - 1] * sn;  ko = kn * c + ksh[d - 1] * sn; }
    else       { qo = qn * c - qs[d + 1] * sn;  ko = kn * c - ksh[d + 1] * sn; }

    size_t o = ((size_t)h * S_TOT + s) * HDIM + d;
    g_Q[o] = qo * QSCALE;
    g_K[o] = ko;
    g_V[o] = v;
}

// ======================= flash attention (warp-specialized) =================
// 8 warps: 0-3 compute (16 q rows each), 4-7 load K/V double-buffered.
// smem bytes: Ks[2]: 0 / 33792 (64x132 tf32); Vt[2]: 67584 / +34816 (128x68);
//             Ps: 137216 (64x68).
#define KS_B   33792
#define VT_B   34816
#define VT_OFF 67584
#define PS_OFF 137216
#define FLASH_SMEM_BYTES 154624

__device__ __forceinline__ void flash_load_tile(
    const float* __restrict__ Kg, const float* __restrict__ Vg,
    uint32_t ksb, uint32_t vtb, int lt)
{
#pragma unroll
    for (int l = 0; l < 16; l++) {
        int idx = lt + l * 128;
        int r = idx >> 5, c = (idx & 31) << 2;
        float4 kv = *(const float4*)(Kg + (size_t)r * HDIM + c);
        STS128(ksb + (uint32_t)(r * 132 + c) * 4,
               f2tf(kv.x), f2tf(kv.y), f2tf(kv.z), f2tf(kv.w));
        float4 vv = *(const float4*)(Vg + (size_t)r * HDIM + c);
        uint32_t b0 = vtb + (uint32_t)(c * 68 + r) * 4;
        STS32(b0,            f2tf(vv.x));
        STS32(b0 + 68 * 4,   f2tf(vv.y));
        STS32(b0 + 136 * 4,  f2tf(vv.z));
        STS32(b0 + 204 * 4,  f2tf(vv.w));
    }
}

__global__ __launch_bounds__(256, 1) void flash_ws_kernel()
{
    extern __shared__ unsigned fsm[];
    const uint32_t su = smem_u32(fsm);

    const int qt = blockIdx.x, h = blockIdx.y;
    const int t = threadIdx.x, lane = t & 31, wid = t >> 5;
    const float* Kg0 = g_K + (size_t)h * S_TOT * HDIM;
    const float* Vg0 = g_V + (size_t)h * S_TOT * HDIM;

    // ---- compute-warp state
    const int g = lane >> 2, t4 = lane & 3;
    const int qb = (wid & 3) * 16;
    unsigned qf[16][4];
    float o[16][4];
    float mrow[2] = {-1e30f, -1e30f}, lrow[2] = {0.f, 0.f};

    // ldmatrix address offsets (word*4 = bytes), relative to region base
    const int brow = (lane & 7) + ((lane >> 4) & 1) * 8;
    const int bcol = ((lane >> 3) & 1) * 4;
    const int parow = (lane & 7) + ((lane >> 3) & 1) * 8;
    const int pacol = (lane >> 4) * 4;
    uint32_t okk[4], ovv[8], opa;
#pragma unroll
    for (int p = 0; p < 4; p++) okk[p] = (uint32_t)((p * 16 + brow) * 132 + bcol) * 4;
#pragma unroll
    for (int p = 0; p < 8; p++) ovv[p] = (uint32_t)((p * 16 + brow) * 68 + bcol) * 4;
    opa = (uint32_t)((qb + parow) * 68 + pacol) * 4;

    if (wid < 4) {
        const float* Qg = g_Q + ((size_t)h * S_TOT + qt * 64) * HDIM;
#pragma unroll
        for (int ks = 0; ks < 16; ks++) {
            int k = ks * 8;
            qf[ks][0] = f2tf(Qg[(size_t)(qb + g) * HDIM + k + t4]);
            qf[ks][1] = f2tf(Qg[(size_t)(qb + g + 8) * HDIM + k + t4]);
            qf[ks][2] = f2tf(Qg[(size_t)(qb + g) * HDIM + k + t4 + 4]);
            qf[ks][3] = f2tf(Qg[(size_t)(qb + g + 8) * HDIM + k + t4 + 4]);
        }
#pragma unroll
        for (int dt = 0; dt < 16; dt++)
#pragma unroll
            for (int c = 0; c < 4; c++) o[dt][c] = 0.f;
    } else {
        flash_load_tile(Kg0, Vg0, su, su + VT_OFF, t - 128);
    }
    __syncthreads();

    const int NT = S_TOT / 64;   // 40
    for (int kt = 0; kt < NT; kt++) {
        const int b = kt & 1;
        if (wid >= 4) {
            if (kt + 1 < NT)
                flash_load_tile(Kg0 + (size_t)(kt + 1) * 64 * HDIM,
                                Vg0 + (size_t)(kt + 1) * 64 * HDIM,
                                su + (b ^ 1) * KS_B,
                                su + VT_OFF + (b ^ 1) * VT_B, t - 128);
        } else {
            const uint32_t ksb = su + b * KS_B;
            const uint32_t vtb = su + VT_OFF + b * VT_B;
            const uint32_t psb = su + PS_OFF;

            // ---- S = Q K^T
            float sc[8][4];
#pragma unroll
            for (int nt = 0; nt < 8; nt++)
#pragma unroll
                for (int c = 0; c < 4; c++) sc[nt][c] = 0.f;
#pragma unroll
            for (int ks = 0; ks < 16; ks++) {
                unsigned bf[8][2];
#pragma unroll
                for (int p = 0; p < 4; p++)
                    LDSM4(bf[2 * p][0], bf[2 * p][1], bf[2 * p + 1][0],
                          bf[2 * p + 1][1], ksb + okk[p] + ks * 32);
#pragma unroll
                for (int nt = 0; nt < 8; nt++)
                    mma8(sc[nt], qf[ks], bf[nt]);
            }

            // ---- online softmax
            float mx0 = -1e30f, mx1 = -1e30f;
#pragma unroll
            for (int nt = 0; nt < 8; nt++) {
                mx0 = fmaxf(mx0, fmaxf(sc[nt][0], sc[nt][1]));
                mx1 = fmaxf(mx1, fmaxf(sc[nt][2], sc[nt][3]));
            }
            mx0 = fmaxf(mx0, __shfl_xor_sync(0xffffffffu, mx0, 1));
            mx0 = fmaxf(mx0, __shfl_xor_sync(0xffffffffu, mx0, 2));
            mx1 = fmaxf(mx1, __shfl_xor_sync(0xffffffffu, mx1, 1));
            mx1 = fmaxf(mx1, __shfl_xor_sync(0xffffffffu, mx1, 2));
            float m0n = fmaxf(mrow[0], mx0), m1n = fmaxf(mrow[1], mx1);
            float a0 = __expf(mrow[0] - m0n), a1 = __expf(mrow[1] - m1n);
            mrow[0] = m0n; mrow[1] = m1n;

            float rs0 = 0.f, rs1 = 0.f;
#pragma unroll
            for (int nt = 0; nt < 8; nt++) {
                sc[nt][0] = __expf(sc[nt][0] - m0n);
                sc[nt][1] = __expf(sc[nt][1] - m0n);
                sc[nt][2] = __expf(sc[nt][2] - m1n);
                sc[nt][3] = __expf(sc[nt][3] - m1n);
                rs0 += sc[nt][0] + sc[nt][1];
                rs1 += sc[nt][2] + sc[nt][3];
            }
            rs0 += __shfl_xor_sync(0xffffffffu, rs0, 1);
            rs0 += __shfl_xor_sync(0xffffffffu, rs0, 2);
            rs1 += __shfl_xor_sync(0xffffffffu, rs1, 1);
            rs1 += __shfl_xor_sync(0xffffffffu, rs1, 2);
            lrow[0] = lrow[0] * a0 + rs0;
            lrow[1] = lrow[1] * a1 + rs1;

#pragma unroll
            for (int dt = 0; dt < 16; dt++) {
                o[dt][0] *= a0; o[dt][1] *= a0;
                o[dt][2] *= a1; o[dt][3] *= a1;
            }

            // ---- P to smem (tf32)
#pragma unroll
            for (int nt = 0; nt < 8; nt++) {
                uint32_t pb = psb + (uint32_t)((qb + g) * 68 + nt * 8 + t4 * 2) * 4;
                STS32(pb,     f2tf(sc[nt][0]));
                STS32(pb + 4, f2tf(sc[nt][1]));
                STS32(pb + 8 * 68 * 4,     f2tf(sc[nt][2]));
                STS32(pb + 8 * 68 * 4 + 4, f2tf(sc[nt][3]));
            }
            __syncwarp();

            // ---- O += P V
#pragma unroll
            for (int ks = 0; ks < 8; ks++) {
                unsigned pa[4];
                LDSM4(pa[0], pa[1], pa[2], pa[3], psb + opa + ks * 32);
#pragma unroll
                for (int p = 0; p < 8; p++) {
                    unsigned vf0[2], vf1[2];
                    LDSM4(vf0[0], vf0[1], vf1[0], vf1[1], vtb + ovv[p] + ks * 32);
                    mma8(o[2 * p], pa, vf0);
                    mma8(o[2 * p + 1], pa, vf1);
                }
            }
        }
        __syncthreads();
    }

    if (wid < 4) {
        float inv0 = 1.0f / lrow[0], inv1 = 1.0f / lrow[1];
        int s0 = qt * 64 + qb + g;
        float* dst0 = g_O + (size_t)s0 * DIMK + h * HDIM;
        float* dst1 = dst0 + (size_t)8 * DIMK;
#pragma unroll
        for (int dt = 0; dt < 16; dt++) {
            int d = dt * 8 + t4 * 2;
            *(float2*)(dst0 + d) = make_float2(o[dt][0] * inv0, o[dt][1] * inv0);
            *(float2*)(dst1 + d) = make_float2(o[dt][2] * inv1, o[dt][3] * inv1);
        }
    }
}

// ---------------- launch ----------------------------------------------------
extern "C" void kernel_launch(void* const* d_in, const int* in_sizes, int n_in,
                              void* d_out, int out_size)
{
    const float* hid       = (const float*)d_in[0];
    const float* enc       = (const float*)d_in[1];
    const float* cosT      = (const float*)d_in[2];
    const float* sinT      = (const float*)d_in[3];
    const float* w_qkv     = (const float*)d_in[4];
    const float* b_qkv     = (const float*)d_in[5];
    const float* w_add     = (const float*)d_in[6];
    const float* b_add     = (const float*)d_in[7];
    const float* nq        = (const float*)d_in[8];
    const float* nk        = (const float*)d_in[9];
    const float* naq       = (const float*)d_in[10];
    const float* nak       = (const float*)d_in[11];
    const float* w_out     = (const float*)d_in[12];
    const float* b_out     = (const float*)d_in[13];
    const float* w_add_out = (const float*)d_in[14];
    const float* b_add_out = (const float*)d_in[15];
    float* out = (float*)d_out;

    static bool attr_done = false;
    if (!attr_done) {
        cudaFuncSetAttribute(gemm_qkv_kernel,
            cudaFuncAttributeMaxDynamicSharedMemorySize, GEMM_SMEM_BYTES);
        cudaFuncSetAttribute(gemm_out_kernel,
            cudaFuncAttributeMaxDynamicSharedMemorySize, GEMM_SMEM_BYTES);
        cudaFuncSetAttribute(flash_ws_kernel,
            cudaFuncAttributeMaxDynamicSharedMemorySize, FLASH_SMEM_BYTES);
        attr_done = true;
    }

    gemm_qkv_kernel<<<dim3(E3 / 128, S_TOT / 128), 256, GEMM_SMEM_BYTES>>>(
        hid, enc, w_qkv, b_qkv, w_add, b_add);

    norm_rope_kernel<<<dim3(S_TOT, NHEADS), 128>>>(cosT, sinT, nq, nk, naq, nak);

    flash_ws_kernel<<<dim3(S_TOT / 64, NHEADS), 256, FLASH_SMEM_BYTES>>>();

    gemm_out_kernel<<<dim3(DIMK / 128, S_TOT / 128), 256, GEMM_SMEM_BYTES>>>(
        w_out, b_out, w_add_out, b_add_out, out);
}

// round 5
// speedup vs baseline: 4.1022x; 1.0123x over previous
#include <cuda_runtime.h>
#include <cstdint>

#define S_TOT  2560
#define S_TXTC 512
#define S_IMGC 2048
#define DIMK   3072
#define NHEADS 24
#define HDIM   128
#define E3     9216
#define EPSV   1e-6f
#define QSCALE 0.088388347648318447f   // 1/sqrt(128)

// ---------------- scratch ---------------------------------------------------
static __device__ float g_qkv[S_TOT * E3];
static __device__ float g_Q[NHEADS * S_TOT * HDIM];
static __device__ float g_K[NHEADS * S_TOT * HDIM];
static __device__ float g_V[NHEADS * S_TOT * HDIM];
static __device__ float g_O[S_TOT * DIMK];

// ---------------- helpers ---------------------------------------------------
__device__ __forceinline__ unsigned f2tf(float x) {
    unsigned u;
    asm("cvt.rna.tf32.f32 %0, %1;" : "=r"(u) : "f"(x));
    return u;
}
__device__ __forceinline__ unsigned u2tf(unsigned x) {
    unsigned u;
    asm("cvt.rna.tf32.f32 %0, %1;" : "=r"(u) : "f"(__uint_as_float(x)));
    return u;
}
__device__ __forceinline__ uint32_t smem_u32(const void* p) {
    uint32_t a;
    asm("{ .reg .u64 t; cvta.to.shared.u64 t, %1; cvt.u32.u64 %0, t; }"
        : "=r"(a) : "l"(p));
    return a;
}
__device__ __forceinline__ void mma8(float (&d)[4], const unsigned (&a)[4],
                                     const unsigned (&b)[2]) {
    asm volatile(
        "mma.sync.aligned.m16n8k8.row.col.f32.tf32.tf32.f32 "
        "{%0,%1,%2,%3}, {%4,%5,%6,%7}, {%8,%9}, {%0,%1,%2,%3};\n"
        : "+f"(d[0]), "+f"(d[1]), "+f"(d[2]), "+f"(d[3])
        : "r"(a[0]), "r"(a[1]), "r"(a[2]), "r"(a[3]), "r"(b[0]), "r"(b[1]));
}
#define LDSM4(r0, r1, r2, r3, addr)                                            \
    asm volatile("ldmatrix.sync.aligned.m8n8.x4.shared.b16 {%0,%1,%2,%3}, [%4];" \
                 : "=r"(r0), "=r"(r1), "=r"(r2), "=r"(r3) : "r"(addr))
#define STS128(addr, x, y, z, w)                                               \
    asm volatile("st.shared.v4.b32 [%0], {%1,%2,%3,%4};"                       \
                 :: "r"(addr), "r"(x), "r"(y), "r"(z), "r"(w) : "memory")
#define STS32(addr, x)                                                         \
    asm volatile("st.shared.b32 [%0], %1;" :: "r"(addr), "r"(x) : "memory")
__device__ __forceinline__ void cp16(uint32_t s, const void* g) {
    asm volatile("cp.async.cg.shared.global [%0], [%1], 16;" :: "r"(s), "l"(g));
}
#define CP_COMMIT() asm volatile("cp.async.commit_group;" ::: "memory")
#define CP_WAIT2()  asm volatile("cp.async.wait_group 2;" ::: "memory")

// =================== GEMM: 128x256 tile, BK=32, cp.async 4-stage ============
// smem: A stages 4 x 16KB @0, B stages 4 x 32KB @64KB. Rows of 128B,
// 16B-chunk XOR swizzle: chunk' = chunk ^ (row & 7).
#define AST_B 16384
#define BST_B 32768
#define GEMM_SMEM_BYTES (4 * AST_B + 4 * BST_B)   // 196608

__device__ __forceinline__ void gemm_issue_stage(
    const float* __restrict__ A, const float* __restrict__ W,
    uint32_t su, int slot, int kk, int t)
{
    const uint32_t sA = su + slot * AST_B;
    const uint32_t sB = su + 4 * AST_B + slot * BST_B;
#pragma unroll
    for (int l = 0; l < 4; l++) {
        int idx = t + l * 256;
        int row = idx >> 3, c = idx & 7;
        cp16(sA + row * 128 + ((c ^ (row & 7)) << 4),
             A + (size_t)row * DIMK + kk + c * 4);
    }
#pragma unroll
    for (int l = 0; l < 8; l++) {
        int idx = t + l * 256;
        int row = idx >> 3, c = idx & 7;
        cp16(sB + row * 128 + ((c ^ (row & 7)) << 4),
             W + (size_t)row * DIMK + kk + c * 4);
    }
    CP_COMMIT();
}

__device__ __forceinline__ void gemm_tf32_main(
    const float* __restrict__ A, const float* __restrict__ W,
    uint32_t su, float (&acc)[4][8][4], int t)
{
    const int lane = t & 31, wid = t >> 5;
    const int wm = wid >> 2, wn = wid & 3;      // 2 x 4 warps, 64x64 tiles
    const int arow = (lane & 7) + ((lane >> 3) & 1) * 8;
    const int asel = lane >> 4;                 // 0/1 -> +16B
    const int brow = (lane & 7) + ((lane >> 4) & 1) * 8;
    const int bsel = (lane >> 3) & 1;

    gemm_issue_stage(A, W, su, 0, 0, t);
    gemm_issue_stage(A, W, su, 1, 32, t);
    gemm_issue_stage(A, W, su, 2, 64, t);

    const int NST = DIMK / 32;   // 96
    for (int i = 0; i < NST; i++) {
        CP_WAIT2();
        __syncthreads();
        if (i + 3 < NST)
            gemm_issue_stage(A, W, su, (i + 3) & 3, (i + 3) * 32, t);

        const int slot = i & 3;
        const uint32_t cA = su + slot * AST_B;
        const uint32_t cB = su + 4 * AST_B + slot * BST_B;
#pragma unroll
        for (int ks = 0; ks < 4; ks++) {
            unsigned af[4][4], bf[8][2];
#pragma unroll
            for (int mt = 0; mt < 4; mt++) {
                int r = wm * 64 + mt * 16 + arow;
                int c = ks * 2 + asel;
                LDSM4(af[mt][0], af[mt][1], af[mt][2], af[mt][3],
                      cA + r * 128 + ((c ^ (r & 7)) << 4));
            }
#pragma unroll
            for (int p = 0; p < 4; p++) {
                int r = wn * 64 + p * 16 + brow;
                int c = ks * 2 + bsel;
                LDSM4(bf[2 * p][0], bf[2 * p][1], bf[2 * p + 1][0],
                      bf[2 * p + 1][1], cB + r * 128 + ((c ^ (r & 7)) << 4));
            }
#pragma unroll
            for (int mt = 0; mt < 4; mt++)
#pragma unroll
                for (int q = 0; q < 4; q++) af[mt][q] = u2tf(af[mt][q]);
#pragma unroll
            for (int nt = 0; nt < 8; nt++) {
                bf[nt][0] = u2tf(bf[nt][0]);
                bf[nt][1] = u2tf(bf[nt][1]);
            }
#pragma unroll
            for (int mt = 0; mt < 4; mt++)
#pragma unroll
                for (int nt = 0; nt < 8; nt++)
                    mma8(acc[mt][nt], af[mt], bf[nt]);
        }
        __syncthreads();
    }
}

// ---------------- kernel 1: QKV projection ----------------------------------
__global__ __launch_bounds__(256, 1) void gemm_qkv_kernel(
    const float* __restrict__ x_img, const float* __restrict__ x_txt,
    const float* __restrict__ w_img, const float* __restrict__ b_img,
    const float* __restrict__ w_txt, const float* __restrict__ b_txt)
{
    extern __shared__ unsigned gsm[];
    const uint32_t su = smem_u32(gsm);
    const int m0 = blockIdx.y * 128;
    const int n0 = blockIdx.x * 256;
    const bool txt = (m0 < S_TXTC);
    const float* A    = txt ? (x_txt + (size_t)m0 * DIMK)
                            : (x_img + (size_t)(m0 - S_TXTC) * DIMK);
    const float* W    = (txt ? w_txt : w_img) + (size_t)n0 * DIMK;
    const float* bias = txt ? b_txt : b_img;

    const int t = threadIdx.x;
    float acc[4][8][4];
#pragma unroll
    for (int i = 0; i < 4; i++)
#pragma unroll
        for (int j = 0; j < 8; j++)
#pragma unroll
            for (int c = 0; c < 4; c++) acc[i][j][c] = 0.f;

    gemm_tf32_main(A, W, su, acc, t);

    const int lane = t & 31, wid = t >> 5;
    const int g = lane >> 2, t4 = lane & 3;
    const int wm = wid >> 2, wn = wid & 3;
#pragma unroll
    for (int mt = 0; mt < 4; mt++) {
        int r0 = m0 + wm * 64 + mt * 16 + g;
#pragma unroll
        for (int nt = 0; nt < 8; nt++) {
            int c = n0 + wn * 64 + nt * 8 + t4 * 2;
            float2 v0 = make_float2(acc[mt][nt][0] + bias[c],
                                    acc[mt][nt][1] + bias[c + 1]);
            float2 v1 = make_float2(acc[mt][nt][2] + bias[c],
                                    acc[mt][nt][3] + bias[c + 1]);
            *(float2*)(g_qkv + (size_t)r0 * E3 + c) = v0;
            *(float2*)(g_qkv + (size_t)(r0 + 8) * E3 + c) = v1;
        }
    }
}

// ---------------- kernel 4: output projections + scatter --------------------
__global__ __launch_bounds__(256, 1) void gemm_out_kernel(
    const float* __restrict__ w_img, const float* __restrict__ b_img,
    const float* __restrict__ w_txt, const float* __restrict__ b_txt,
    float* __restrict__ out)
{
    extern __shared__ unsigned gsm[];
    const uint32_t su = smem_u32(gsm);
    const int m0 = blockIdx.y * 128;
    const int n0 = blockIdx.x * 256;
    const bool txt = (m0 < S_TXTC);
    const float* A    = g_O + (size_t)m0 * DIMK;
    const float* W    = (txt ? w_txt : w_img) + (size_t)n0 * DIMK;
    const float* bias = txt ? b_txt : b_img;

    const int t = threadIdx.x;
    float acc[4][8][4];
#pragma unroll
    for (int i = 0; i < 4; i++)
#pragma unroll
        for (int j = 0; j < 8; j++)
#pragma unroll
            for (int c = 0; c < 4; c++) acc[i][j][c] = 0.f;

    gemm_tf32_main(A, W, su, acc, t);

    const int lane = t & 31, wid = t >> 5;
    const int g = lane >> 2, t4 = lane & 3;
    const int wm = wid >> 2, wn = wid & 3;
#pragma unroll
    for (int mt = 0; mt < 4; mt++) {
        int s = m0 + wm * 64 + mt * 16 + g;
        int orow0 = txt ? (S_IMGC + s) : (s - S_TXTC);
        int orow1 = orow0 + 8;
#pragma unroll
        for (int nt = 0; nt < 8; nt++) {
            int c = n0 + wn * 64 + nt * 8 + t4 * 2;
            float2 v0 = make_float2(acc[mt][nt][0] + bias[c],
                                    acc[mt][nt][1] + bias[c + 1]);
            float2 v1 = make_float2(acc[mt][nt][2] + bias[c],
                                    acc[mt][nt][3] + bias[c + 1]);
            *(float2*)(out + (size_t)orow0 * DIMK + c) = v0;
            *(float2*)(out + (size_t)orow1 * DIMK + c) = v1;
        }
    }
}

// ---------------- kernel 2: RMSNorm + RoPE + scatter ------------------------
__global__ __launch_bounds__(128) void norm_rope_kernel(
    const float* __restrict__ cosT, const float* __restrict__ sinT,
    const float* __restrict__ nq,  const float* __restrict__ nk,
    const float* __restrict__ naq, const float* __restrict__ nak)
{
    const int s = blockIdx.x, h = blockIdx.y, d = threadIdx.x;
    const float* row = g_qkv + (size_t)s * E3 + h * HDIM;
    float q = row[d];
    float k = row[DIMK + d];
    float v = row[2 * DIMK + d];

    float sq = q * q, sk = k * k;
#pragma unroll
    for (int o = 16; o > 0; o >>= 1) {
        sq += __shfl_xor_sync(0xffffffffu, sq, o);
        sk += __shfl_xor_sync(0xffffffffu, sk, o);
    }
    __shared__ float redq[4], redk[4];
    if ((d & 31) == 0) { redq[d >> 5] = sq; redk[d >> 5] = sk; }
    __syncthreads();
    sq = redq[0] + redq[1] + redq[2] + redq[3];
    sk = redk[0] + redk[1] + redk[2] + redk[3];

    float rq = rsqrtf(sq * (1.0f / HDIM) + EPSV);
    float rk = rsqrtf(sk * (1.0f / HDIM) + EPSV);
    const bool txt = (s < S_TXTC);
    float qn = q * rq * (txt ? naq[d] : nq[d]);
    float kn = k * rk * (txt ? nak[d] : nk[d]);

    __shared__ float qs[128], ksh[128];
    qs[d] = qn; ksh[d] = kn;
    __syncthreads();

    const int i = d >> 1;
    float c  = cosT[s * 64 + i];
    float sn = sinT[s * 64 + i];
    float qo, ko;
    if (d & 1) { qo = qn * c + qs[d - 1] * sn;  ko = kn * c + ksh[d - 1] * sn; }
    else       { qo = qn * c - qs[d + 1] * sn;  ko = kn * c - ksh[d + 1] * sn; }

    size_t o = ((size_t)h * S_TOT + s) * HDIM + d;
    g_Q[o] = qo * QSCALE;
    g_K[o] = ko;
    g_V[o] = v;
}

// ======================= flash attention (warp-specialized) =================
#define KS_B   33792
#define VT_B   34816
#define VT_OFF 67584
#define PS_OFF 137216
#define FLASH_SMEM_BYTES 154624

__device__ __forceinline__ void flash_load_tile(
    const float* __restrict__ Kg, const float* __restrict__ Vg,
    uint32_t ksb, uint32_t vtb, int lt)
{
#pragma unroll
    for (int l = 0; l < 16; l++) {
        int idx = lt + l * 128;
        int r = idx >> 5, c = (idx & 31) << 2;
        float4 kv = *(const float4*)(Kg + (size_t)r * HDIM + c);
        STS128(ksb + (uint32_t)(r * 132 + c) * 4,
               f2tf(kv.x), f2tf(kv.y), f2tf(kv.z), f2tf(kv.w));
        float4 vv = *(const float4*)(Vg + (size_t)r * HDIM + c);
        uint32_t b0 = vtb + (uint32_t)(c * 68 + r) * 4;
        STS32(b0,            f2tf(vv.x));
        STS32(b0 + 68 * 4,   f2tf(vv.y));
        STS32(b0 + 136 * 4,  f2tf(vv.z));
        STS32(b0 + 204 * 4,  f2tf(vv.w));
    }
}

__global__ __launch_bounds__(256, 1) void flash_ws_kernel()
{
    extern __shared__ unsigned fsm[];
    const uint32_t su = smem_u32(fsm);

    const int qt = blockIdx.x, h = blockIdx.y;
    const int t = threadIdx.x, lane = t & 31, wid = t >> 5;
    const float* Kg0 = g_K + (size_t)h * S_TOT * HDIM;
    const float* Vg0 = g_V + (size_t)h * S_TOT * HDIM;

    const int g = lane >> 2, t4 = lane & 3;
    const int qb = (wid & 3) * 16;
    unsigned qf[16][4];
    float o[16][4];
    float mrow[2] = {-1e30f, -1e30f}, lrow[2] = {0.f, 0.f};

    const int brow = (lane & 7) + ((lane >> 4) & 1) * 8;
    const int bcol = ((lane >> 3) & 1) * 4;
    const int parow = (lane & 7) + ((lane >> 3) & 1) * 8;
    const int pacol = (lane >> 4) * 4;
    uint32_t okk[4], ovv[8], opa;
#pragma unroll
    for (int p = 0; p < 4; p++) okk[p] = (uint32_t)((p * 16 + brow) * 132 + bcol) * 4;
#pragma unroll
    for (int p = 0; p < 8; p++) ovv[p] = (uint32_t)((p * 16 + brow) * 68 + bcol) * 4;
    opa = (uint32_t)((qb + parow) * 68 + pacol) * 4;

    if (wid < 4) {
        const float* Qg = g_Q + ((size_t)h * S_TOT + qt * 64) * HDIM;
#pragma unroll
        for (int ks = 0; ks < 16; ks++) {
            int k = ks * 8;
            qf[ks][0] = f2tf(Qg[(size_t)(qb + g) * HDIM + k + t4]);
            qf[ks][1] = f2tf(Qg[(size_t)(qb + g + 8) * HDIM + k + t4]);
            qf[ks][2] = f2tf(Qg[(size_t)(qb + g) * HDIM + k + t4 + 4]);
            qf[ks][3] = f2tf(Qg[(size_t)(qb + g + 8) * HDIM + k + t4 + 4]);
        }
#pragma unroll
        for (int dt = 0; dt < 16; dt++)
#pragma unroll
            for (int c = 0; c < 4; c++) o[dt][c] = 0.f;
    } else {
        flash_load_tile(Kg0, Vg0, su, su + VT_OFF, t - 128);
    }
    __syncthreads();

    const int NT = S_TOT / 64;   // 40
    for (int kt = 0; kt < NT; kt++) {
        const int b = kt & 1;
        if (wid >= 4) {
            if (kt + 1 < NT)
                flash_load_tile(Kg0 + (size_t)(kt + 1) * 64 * HDIM,
                                Vg0 + (size_t)(kt + 1) * 64 * HDIM,
                                su + (b ^ 1) * KS_B,
                                su + VT_OFF + (b ^ 1) * VT_B, t - 128);
        } else {
            const uint32_t ksb = su + b * KS_B;
            const uint32_t vtb = su + VT_OFF + b * VT_B;
            const uint32_t psb = su + PS_OFF;

            float sc[8][4];
#pragma unroll
            for (int nt = 0; nt < 8; nt++)
#pragma unroll
                for (int c = 0; c < 4; c++) sc[nt][c] = 0.f;
#pragma unroll
            for (int ks = 0; ks < 16; ks++) {
                unsigned bf[8][2];
#pragma unroll
                for (int p = 0; p < 4; p++)
                    LDSM4(bf[2 * p][0], bf[2 * p][1], bf[2 * p + 1][0],
                          bf[2 * p + 1][1], ksb + okk[p] + ks * 32);
#pragma unroll
                for (int nt = 0; nt < 8; nt++)
                    mma8(sc[nt], qf[ks], bf[nt]);
            }

            float mx0 = -1e30f, mx1 = -1e30f;
#pragma unroll
            for (int nt = 0; nt < 8; nt++) {
                mx0 = fmaxf(mx0, fmaxf(sc[nt][0], sc[nt][1]));
                mx1 = fmaxf(mx1, fmaxf(sc[nt][2], sc[nt][3]));
            }
            mx0 = fmaxf(mx0, __shfl_xor_sync(0xffffffffu, mx0, 1));
            mx0 = fmaxf(mx0, __shfl_xor_sync(0xffffffffu, mx0, 2));
            mx1 = fmaxf(mx1, __shfl_xor_sync(0xffffffffu, mx1, 1));
            mx1 = fmaxf(mx1, __shfl_xor_sync(0xffffffffu, mx1, 2));
            float m0n = fmaxf(mrow[0], mx0), m1n = fmaxf(mrow[1], mx1);
            float a0 = __expf(mrow[0] - m0n), a1 = __expf(mrow[1] - m1n);
            mrow[0] = m0n; mrow[1] = m1n;

            float rs0 = 0.f, rs1 = 0.f;
#pragma unroll
            for (int nt = 0; nt < 8; nt++) {
                sc[nt][0] = __expf(sc[nt][0] - m0n);
                sc[nt][1] = __expf(sc[nt][1] - m0n);
                sc[nt][2] = __expf(sc[nt][2] - m1n);
                sc[nt][3] = __expf(sc[nt][3] - m1n);
                rs0 += sc[nt][0] + sc[nt][1];
                rs1 += sc[nt][2] + sc[nt][3];
            }
            rs0 += __shfl_xor_sync(0xffffffffu, rs0, 1);
            rs0 += __shfl_xor_sync(0xffffffffu, rs0, 2);
            rs1 += __shfl_xor_sync(0xffffffffu, rs1, 1);
            rs1 += __shfl_xor_sync(0xffffffffu, rs1, 2);
            lrow[0] = lrow[0] * a0 + rs0;
            lrow[1] = lrow[1] * a1 + rs1;

#pragma unroll
            for (int dt = 0; dt < 16; dt++) {
                o[dt][0] *= a0; o[dt][1] *= a0;
                o[dt][2] *= a1; o[dt][3] *= a1;
            }

#pragma unroll
            for (int nt = 0; nt < 8; nt++) {
                uint32_t pb = psb + (uint32_t)((qb + g) * 68 + nt * 8 + t4 * 2) * 4;
                STS32(pb,     f2tf(sc[nt][0]));
                STS32(pb + 4, f2tf(sc[nt][1]));
                STS32(pb + 8 * 68 * 4,     f2tf(sc[nt][2]));
                STS32(pb + 8 * 68 * 4 + 4, f2tf(sc[nt][3]));
            }
            __syncwarp();

#pragma unroll
            for (int ks = 0; ks < 8; ks++) {
                unsigned pa[4];
                LDSM4(pa[0], pa[1], pa[2], pa[3], psb + opa + ks * 32);
#pragma unroll
                for (int p = 0; p < 8; p++) {
                    unsigned vf0[2], vf1[2];
                    LDSM4(vf0[0], vf0[1], vf1[0], vf1[1], vtb + ovv[p] + ks * 32);
                    mma8(o[2 * p], pa, vf0);
                    mma8(o[2 * p + 1], pa, vf1);
                }
            }
        }
        __syncthreads();
    }

    if (wid < 4) {
        float inv0 = 1.0f / lrow[0], inv1 = 1.0f / lrow[1];
        int s0 = qt * 64 + qb + g;
        float* dst0 = g_O + (size_t)s0 * DIMK + h * HDIM;
        float* dst1 = dst0 + (size_t)8 * DIMK;
#pragma unroll
        for (int dt = 0; dt < 16; dt++) {
            int d = dt * 8 + t4 * 2;
            *(float2*)(dst0 + d) = make_float2(o[dt][0] * inv0, o[dt][1] * inv0);
            *(float2*)(dst1 + d) = make_float2(o[dt][2] * inv1, o[dt][3] * inv1);
        }
    }
}

// ---------------- launch ----------------------------------------------------
extern "C" void kernel_launch(void* const* d_in, const int* in_sizes, int n_in,
                              void* d_out, int out_size)
{
    const float* hid       = (const float*)d_in[0];
    const float* enc       = (const float*)d_in[1];
    const float* cosT      = (const float*)d_in[2];
    const float* sinT      = (const float*)d_in[3];
    const float* w_qkv     = (const float*)d_in[4];
    const float* b_qkv     = (const float*)d_in[5];
    const float* w_add     = (const float*)d_in[6];
    const float* b_add     = (const float*)d_in[7];
    const float* nq        = (const float*)d_in[8];
    const float* nk        = (const float*)d_in[9];
    const float* naq       = (const float*)d_in[10];
    const float* nak       = (const float*)d_in[11];
    const float* w_out     = (const float*)d_in[12];
    const float* b_out     = (const float*)d_in[13];
    const float* w_add_out = (const float*)d_in[14];
    const float* b_add_out = (const float*)d_in[15];
    float* out = (float*)d_out;

    static bool attr_done = false;
    if (!attr_done) {
        cudaFuncSetAttribute(gemm_qkv_kernel,
            cudaFuncAttributeMaxDynamicSharedMemorySize, GEMM_SMEM_BYTES);
        cudaFuncSetAttribute(gemm_out_kernel,
            cudaFuncAttributeMaxDynamicSharedMemorySize, GEMM_SMEM_BYTES);
        cudaFuncSetAttribute(flash_ws_kernel,
            cudaFuncAttributeMaxDynamicSharedMemorySize, FLASH_SMEM_BYTES);
        attr_done = true;
    }

    gemm_qkv_kernel<<<dim3(E3 / 256, S_TOT / 128), 256, GEMM_SMEM_BYTES>>>(
        hid, enc, w_qkv, b_qkv, w_add, b_add);

    norm_rope_kernel<<<dim3(S_TOT, NHEADS), 128>>>(cosT, sinT, nq, nk, naq, nak);

    flash_ws_kernel<<<dim3(S_TOT / 64, NHEADS), 256, FLASH_SMEM_BYTES>>>();

    gemm_out_kernel<<<dim3(DIMK / 256, S_TOT / 128), 256, GEMM_SMEM_BYTES>>>(
        w_out, b_out, w_add_out, b_add_out, out);
}

// round 6
// speedup vs baseline: 4.4184x; 1.0771x over previous
#include <cuda_runtime.h>
#include <cstdint>

#define S_TOT  2560
#define S_TXTC 512
#define S_IMGC 2048
#define DIMK   3072
#define NHEADS 24
#define HDIM   128
#define E3     9216
#define EPSV   1e-6f
#define QSCALE 0.088388347648318447f   // 1/sqrt(128)

// ---------------- scratch ---------------------------------------------------
static __device__ float g_qkv[S_TOT * E3];
static __device__ float g_Q[NHEADS * S_TOT * HDIM];
static __device__ float g_K[NHEADS * S_TOT * HDIM];
static __device__ float g_V[NHEADS * S_TOT * HDIM];
static __device__ float g_O[S_TOT * DIMK];

// ---------------- helpers ---------------------------------------------------
__device__ __forceinline__ unsigned f2tf(float x) {
    unsigned u;
    asm("cvt.rna.tf32.f32 %0, %1;" : "=r"(u) : "f"(x));
    return u;
}
__device__ __forceinline__ unsigned u2tf(unsigned x) {
    unsigned u;
    asm("cvt.rna.tf32.f32 %0, %1;" : "=r"(u) : "f"(__uint_as_float(x)));
    return u;
}
__device__ __forceinline__ uint32_t smem_u32(const void* p) {
    uint32_t a;
    asm("{ .reg .u64 t; cvta.to.shared.u64 t, %1; cvt.u32.u64 %0, t; }"
        : "=r"(a) : "l"(p));
    return a;
}
__device__ __forceinline__ void mma8(float (&d)[4], const unsigned (&a)[4],
                                     const unsigned (&b)[2]) {
    asm volatile(
        "mma.sync.aligned.m16n8k8.row.col.f32.tf32.tf32.f32 "
        "{%0,%1,%2,%3}, {%4,%5,%6,%7}, {%8,%9}, {%0,%1,%2,%3};\n"
        : "+f"(d[0]), "+f"(d[1]), "+f"(d[2]), "+f"(d[3])
        : "r"(a[0]), "r"(a[1]), "r"(a[2]), "r"(a[3]), "r"(b[0]), "r"(b[1]));
}
#define LDSM4(r0, r1, r2, r3, addr)                                            \
    asm volatile("ldmatrix.sync.aligned.m8n8.x4.shared.b16 {%0,%1,%2,%3}, [%4];" \
                 : "=r"(r0), "=r"(r1), "=r"(r2), "=r"(r3) : "r"(addr))
#define STS32(addr, x)                                                         \
    asm volatile("st.shared.b32 [%0], %1;" :: "r"(addr), "r"(x) : "memory")
__device__ __forceinline__ void cp16(uint32_t s, const void* g) {
    asm volatile("cp.async.cg.shared.global [%0], [%1], 16;" :: "r"(s), "l"(g));
}
#define CP_COMMIT() asm volatile("cp.async.commit_group;" ::: "memory")
#define CP_WAIT2()  asm volatile("cp.async.wait_group 2;" ::: "memory")
#define CP_WAIT0()  asm volatile("cp.async.wait_group 0;" ::: "memory")

// =================== GEMM: 128x256 tile, BK=32, cp.async 4-stage ============
#define AST_B 16384
#define BST_B 32768
#define GEMM_SMEM_BYTES (4 * AST_B + 4 * BST_B)   // 196608

__device__ __forceinline__ void gemm_issue_stage(
    const float* __restrict__ A, const float* __restrict__ W,
    uint32_t su, int slot, int kk, int t)
{
    const uint32_t sA = su + slot * AST_B;
    const uint32_t sB = su + 4 * AST_B + slot * BST_B;
#pragma unroll
    for (int l = 0; l < 4; l++) {
        int idx = t + l * 256;
        int row = idx >> 3, c = idx & 7;
        cp16(sA + row * 128 + ((c ^ (row & 7)) << 4),
             A + (size_t)row * DIMK + kk + c * 4);
    }
#pragma unroll
    for (int l = 0; l < 8; l++) {
        int idx = t + l * 256;
        int row = idx >> 3, c = idx & 7;
        cp16(sB + row * 128 + ((c ^ (row & 7)) << 4),
             W + (size_t)row * DIMK + kk + c * 4);
    }
    CP_COMMIT();
}

__device__ __forceinline__ void gemm_tf32_main(
    const float* __restrict__ A, const float* __restrict__ W,
    uint32_t su, float (&acc)[4][8][4], int t)
{
    const int lane = t & 31, wid = t >> 5;
    const int wm = wid >> 2, wn = wid & 3;      // 2 x 4 warps, 64x64 tiles
    const int arow = (lane & 7) + ((lane >> 3) & 1) * 8;
    const int asel = lane >> 4;
    const int brow = (lane & 7) + ((lane >> 4) & 1) * 8;
    const int bsel = (lane >> 3) & 1;

    gemm_issue_stage(A, W, su, 0, 0, t);
    gemm_issue_stage(A, W, su, 1, 32, t);
    gemm_issue_stage(A, W, su, 2, 64, t);

    const int NST = DIMK / 32;   // 96
    for (int i = 0; i < NST; i++) {
        CP_WAIT2();
        __syncthreads();
        if (i + 3 < NST)
            gemm_issue_stage(A, W, su, (i + 3) & 3, (i + 3) * 32, t);

        const int slot = i & 3;
        const uint32_t cA = su + slot * AST_B;
        const uint32_t cB = su + 4 * AST_B + slot * BST_B;
#pragma unroll
        for (int ks = 0; ks < 4; ks++) {
            unsigned af[4][4], bf[8][2];
#pragma unroll
            for (int mt = 0; mt < 4; mt++) {
                int r = wm * 64 + mt * 16 + arow;
                int c = ks * 2 + asel;
                LDSM4(af[mt][0], af[mt][1], af[mt][2], af[mt][3],
                      cA + r * 128 + ((c ^ (r & 7)) << 4));
            }
#pragma unroll
            for (int p = 0; p < 4; p++) {
                int r = wn * 64 + p * 16 + brow;
                int c = ks * 2 + bsel;
                LDSM4(bf[2 * p][0], bf[2 * p][1], bf[2 * p + 1][0],
                      bf[2 * p + 1][1], cB + r * 128 + ((c ^ (r & 7)) << 4));
            }
#pragma unroll
            for (int mt = 0; mt < 4; mt++)
#pragma unroll
                for (int q = 0; q < 4; q++) af[mt][q] = u2tf(af[mt][q]);
#pragma unroll
            for (int nt = 0; nt < 8; nt++) {
                bf[nt][0] = u2tf(bf[nt][0]);
                bf[nt][1] = u2tf(bf[nt][1]);
            }
#pragma unroll
            for (int mt = 0; mt < 4; mt++)
#pragma unroll
                for (int nt = 0; nt < 8; nt++)
                    mma8(acc[mt][nt], af[mt], bf[nt]);
        }
        // NOTE: no bottom barrier — top barrier of next iter protects slot reuse
    }
}

// ---------------- kernel 1: QKV projection ----------------------------------
__global__ __launch_bounds__(256, 1) void gemm_qkv_kernel(
    const float* __restrict__ x_img, const float* __restrict__ x_txt,
    const float* __restrict__ w_img, const float* __restrict__ b_img,
    const float* __restrict__ w_txt, const float* __restrict__ b_txt)
{
    extern __shared__ unsigned gsm[];
    const uint32_t su = smem_u32(gsm);
    const int m0 = blockIdx.x * 128;     // x = m: consecutive blocks share W
    const int n0 = blockIdx.y * 256;
    const bool txt = (m0 < S_TXTC);
    const float* A    = txt ? (x_txt + (size_t)m0 * DIMK)
                            : (x_img + (size_t)(m0 - S_TXTC) * DIMK);
    const float* W    = (txt ? w_txt : w_img) + (size_t)n0 * DIMK;
    const float* bias = txt ? b_txt : b_img;

    const int t = threadIdx.x;
    float acc[4][8][4];
#pragma unroll
    for (int i = 0; i < 4; i++)
#pragma unroll
        for (int j = 0; j < 8; j++)
#pragma unroll
            for (int c = 0; c < 4; c++) acc[i][j][c] = 0.f;

    gemm_tf32_main(A, W, su, acc, t);

    const int lane = t & 31, wid = t >> 5;
    const int g = lane >> 2, t4 = lane & 3;
    const int wm = wid >> 2, wn = wid & 3;
#pragma unroll
    for (int mt = 0; mt < 4; mt++) {
        int r0 = m0 + wm * 64 + mt * 16 + g;
#pragma unroll
        for (int nt = 0; nt < 8; nt++) {
            int c = n0 + wn * 64 + nt * 8 + t4 * 2;
            float2 v0 = make_float2(acc[mt][nt][0] + bias[c],
                                    acc[mt][nt][1] + bias[c + 1]);
            float2 v1 = make_float2(acc[mt][nt][2] + bias[c],
                                    acc[mt][nt][3] + bias[c + 1]);
            *(float2*)(g_qkv + (size_t)r0 * E3 + c) = v0;
            *(float2*)(g_qkv + (size_t)(r0 + 8) * E3 + c) = v1;
        }
    }
}

// ---------------- kernel 4: output projections + scatter --------------------
__global__ __launch_bounds__(256, 1) void gemm_out_kernel(
    const float* __restrict__ w_img, const float* __restrict__ b_img,
    const float* __restrict__ w_txt, const float* __restrict__ b_txt,
    float* __restrict__ out)
{
    extern __shared__ unsigned gsm[];
    const uint32_t su = smem_u32(gsm);
    const int m0 = blockIdx.x * 128;
    const int n0 = blockIdx.y * 256;
    const bool txt = (m0 < S_TXTC);
    const float* A    = g_O + (size_t)m0 * DIMK;
    const float* W    = (txt ? w_txt : w_img) + (size_t)n0 * DIMK;
    const float* bias = txt ? b_txt : b_img;

    const int t = threadIdx.x;
    float acc[4][8][4];
#pragma unroll
    for (int i = 0; i < 4; i++)
#pragma unroll
        for (int j = 0; j < 8; j++)
#pragma unroll
            for (int c = 0; c < 4; c++) acc[i][j][c] = 0.f;

    gemm_tf32_main(A, W, su, acc, t);

    const int lane = t & 31, wid = t >> 5;
    const int g = lane >> 2, t4 = lane & 3;
    const int wm = wid >> 2, wn = wid & 3;
#pragma unroll
    for (int mt = 0; mt < 4; mt++) {
        int s = m0 + wm * 64 + mt * 16 + g;
        int orow0 = txt ? (S_IMGC + s) : (s - S_TXTC);
        int orow1 = orow0 + 8;
#pragma unroll
        for (int nt = 0; nt < 8; nt++) {
            int c = n0 + wn * 64 + nt * 8 + t4 * 2;
            float2 v0 = make_float2(acc[mt][nt][0] + bias[c],
                                    acc[mt][nt][1] + bias[c + 1]);
            float2 v1 = make_float2(acc[mt][nt][2] + bias[c],
                                    acc[mt][nt][3] + bias[c + 1]);
            *(float2*)(out + (size_t)orow0 * DIMK + c) = v0;
            *(float2*)(out + (size_t)orow1 * DIMK + c) = v1;
        }
    }
}

// ---------------- kernel 2: RMSNorm + RoPE + scatter ------------------------
__global__ __launch_bounds__(128) void norm_rope_kernel(
    const float* __restrict__ cosT, const float* __restrict__ sinT,
    const float* __restrict__ nq,  const float* __restrict__ nk,
    const float* __restrict__ naq, const float* __restrict__ nak)
{
    const int s = blockIdx.x, h = blockIdx.y, d = threadIdx.x;
    const float* row = g_qkv + (size_t)s * E3 + h * HDIM;
    float q = row[d];
    float k = row[DIMK + d];
    float v = row[2 * DIMK + d];

    float sq = q * q, sk = k * k;
#pragma unroll
    for (int o = 16; o > 0; o >>= 1) {
        sq += __shfl_xor_sync(0xffffffffu, sq, o);
        sk += __shfl_xor_sync(0xffffffffu, sk, o);
    }
    __shared__ float redq[4], redk[4];
    if ((d & 31) == 0) { redq[d >> 5] = sq; redk[d >> 5] = sk; }
    __syncthreads();
    sq = redq[0] + redq[1] + redq[2] + redq[3];
    sk = redk[0] + redk[1] + redk[2] + redk[3];

    float rq = rsqrtf(sq * (1.0f / HDIM) + EPSV);
    float rk = rsqrtf(sk * (1.0f / HDIM) + EPSV);
    const bool txt = (s < S_TXTC);
    float qn = q * rq * (txt ? naq[d] : nq[d]);
    float kn = k * rk * (txt ? nak[d] : nk[d]);

    __shared__ float qs[128], ksh[128];
    qs[d] = qn; ksh[d] = kn;
    __syncthreads();

    const int i = d >> 1;
    float c  = cosT[s * 64 + i];
    float sn = sinT[s * 64 + i];
    float qo, ko;
    if (d & 1) { qo = qn * c + qs[d - 1] * sn;  ko = kn * c + ksh[d - 1] * sn; }
    else       { qo = qn * c - qs[d + 1] * sn;  ko = kn * c - ksh[d + 1] * sn; }

    size_t o = ((size_t)h * S_TOT + s) * HDIM + d;
    g_Q[o] = qo * QSCALE;
    g_K[o] = ko;
    g_V[o] = v;
}

// =================== flash v3: 128q-tile, 8 compute warps, cp.async K =======
// smem: Ks[2] raw f32 64x132 (33792 B each); Vt[2] tf32 128x68 (34816 B each);
//       Ps tf32 128x68 (34816 B).
#define KS_B   33792
#define VT_B   34816
#define VT_OFF (2 * KS_B)              // 67584
#define PS_OFF (VT_OFF + 2 * VT_B)     // 137216
#define FLASH_SMEM_BYTES (PS_OFF + VT_B)   // 172032

__device__ __forceinline__ void flash_issue_k(const float* __restrict__ Kg,
                                              uint32_t ksb, int t)
{
#pragma unroll
    for (int l = 0; l < 8; l++) {
        int idx = t + l * 256;
        int r = idx >> 5, c = idx & 31;
        cp16(ksb + (uint32_t)(r * 528 + c * 16), Kg + (size_t)r * HDIM + c * 4);
    }
    CP_COMMIT();
}

__global__ __launch_bounds__(256, 1) void flash_v3_kernel()
{
    extern __shared__ unsigned fsm[];
    const uint32_t su = smem_u32(fsm);

    const int qt = blockIdx.x, h = blockIdx.y;
    const int t = threadIdx.x, lane = t & 31, wid = t >> 5;
    const float* Kg0 = g_K + (size_t)h * S_TOT * HDIM;
    const float* Vg0 = g_V + (size_t)h * S_TOT * HDIM;

    const int g = lane >> 2, t4 = lane & 3;
    const int qb = wid * 16;

    const int brow = (lane & 7) + ((lane >> 4) & 1) * 8;
    const int bcol = ((lane >> 3) & 1) * 4;
    const int parow = (lane & 7) + ((lane >> 3) & 1) * 8;
    const int pacol = (lane >> 4) * 4;
    uint32_t okk[4], ovv[8], opa;
#pragma unroll
    for (int p = 0; p < 4; p++) okk[p] = (uint32_t)((p * 16 + brow) * 132 + bcol) * 4;
#pragma unroll
    for (int p = 0; p < 8; p++) ovv[p] = (uint32_t)((p * 16 + brow) * 68 + bcol) * 4;
    opa = (uint32_t)((qb + parow) * 68 + pacol) * 4;

    // ---- prologue: K tile0 via cp.async, V tile0 manual transpose, Q frags
    flash_issue_k(Kg0, su, t);

    unsigned qf[16][4];
    const float* Qg = g_Q + ((size_t)h * S_TOT + qt * 128) * HDIM;
#pragma unroll
    for (int ks = 0; ks < 16; ks++) {
        int k = ks * 8;
        qf[ks][0] = f2tf(Qg[(size_t)(qb + g) * HDIM + k + t4]);
        qf[ks][1] = f2tf(Qg[(size_t)(qb + g + 8) * HDIM + k + t4]);
        qf[ks][2] = f2tf(Qg[(size_t)(qb + g) * HDIM + k + t4 + 4]);
        qf[ks][3] = f2tf(Qg[(size_t)(qb + g + 8) * HDIM + k + t4 + 4]);
    }

    float4 vr[8];
#pragma unroll
    for (int l = 0; l < 8; l++) {
        int idx = t + l * 256;
        int r = idx >> 5, c = idx & 31;
        vr[l] = *(const float4*)(Vg0 + (size_t)r * HDIM + c * 4);
    }
#pragma unroll
    for (int l = 0; l < 8; l++) {
        int idx = t + l * 256;
        int r = idx >> 5, c = idx & 31;
        uint32_t b0 = su + VT_OFF + (uint32_t)((c * 4) * 68 + r) * 4;
        STS32(b0,           f2tf(vr[l].x));
        STS32(b0 + 68 * 4,  f2tf(vr[l].y));
        STS32(b0 + 136 * 4, f2tf(vr[l].z));
        STS32(b0 + 204 * 4, f2tf(vr[l].w));
    }

    float o[16][4];
#pragma unroll
    for (int dt = 0; dt < 16; dt++)
#pragma unroll
        for (int c = 0; c < 4; c++) o[dt][c] = 0.f;
    float mrow[2] = {-1e30f, -1e30f}, lrow[2] = {0.f, 0.f};

    CP_WAIT0();
    __syncthreads();

    const int NT = S_TOT / 64;   // 40
    for (int kt = 0; kt < NT; kt++) {
        const int b = kt & 1;
        const bool pre = (kt + 1 < NT);
        if (pre) {
            flash_issue_k(Kg0 + (size_t)(kt + 1) * 64 * HDIM,
                          su + (b ^ 1) * KS_B, t);
#pragma unroll
            for (int l = 0; l < 8; l++) {
                int idx = t + l * 256;
                int r = idx >> 5, c = idx & 31;
                vr[l] = *(const float4*)(Vg0 + (size_t)(kt + 1) * 64 * HDIM +
                                         (size_t)r * HDIM + c * 4);
            }
        }

        const uint32_t ksb = su + b * KS_B;
        const uint32_t vtb = su + VT_OFF + b * VT_B;
        const uint32_t psb = su + PS_OFF;

        // ---- S = Q K^T (K raw f32 in smem; cvt after ldmatrix)
        float sc[8][4];
#pragma unroll
        for (int nt = 0; nt < 8; nt++)
#pragma unroll
            for (int c = 0; c < 4; c++) sc[nt][c] = 0.f;
#pragma unroll
        for (int ks = 0; ks < 16; ks++) {
            unsigned bf[8][2];
#pragma unroll
            for (int p = 0; p < 4; p++)
                LDSM4(bf[2 * p][0], bf[2 * p][1], bf[2 * p + 1][0],
                      bf[2 * p + 1][1], ksb + okk[p] + ks * 32);
#pragma unroll
            for (int nt = 0; nt < 8; nt++) {
                bf[nt][0] = u2tf(bf[nt][0]);
                bf[nt][1] = u2tf(bf[nt][1]);
            }
#pragma unroll
            for (int nt = 0; nt < 8; nt++)
                mma8(sc[nt], qf[ks], bf[nt]);
        }

        // ---- online softmax
        float mx0 = -1e30f, mx1 = -1e30f;
#pragma unroll
        for (int nt = 0; nt < 8; nt++) {
            mx0 = fmaxf(mx0, fmaxf(sc[nt][0], sc[nt][1]));
            mx1 = fmaxf(mx1, fmaxf(sc[nt][2], sc[nt][3]));
        }
        mx0 = fmaxf(mx0, __shfl_xor_sync(0xffffffffu, mx0, 1));
        mx0 = fmaxf(mx0, __shfl_xor_sync(0xffffffffu, mx0, 2));
        mx1 = fmaxf(mx1, __shfl_xor_sync(0xffffffffu, mx1, 1));
        mx1 = fmaxf(mx1, __shfl_xor_sync(0xffffffffu, mx1, 2));
        float m0n = fmaxf(mrow[0], mx0), m1n = fmaxf(mrow[1], mx1);
        float a0 = __expf(mrow[0] - m0n), a1 = __expf(mrow[1] - m1n);
        mrow[0] = m0n; mrow[1] = m1n;

        float rs0 = 0.f, rs1 = 0.f;
#pragma unroll
        for (int nt = 0; nt < 8; nt++) {
            sc[nt][0] = __expf(sc[nt][0] - m0n);
            sc[nt][1] = __expf(sc[nt][1] - m0n);
            sc[nt][2] = __expf(sc[nt][2] - m1n);
            sc[nt][3] = __expf(sc[nt][3] - m1n);
            rs0 += sc[nt][0] + sc[nt][1];
            rs1 += sc[nt][2] + sc[nt][3];
        }
        rs0 += __shfl_xor_sync(0xffffffffu, rs0, 1);
        rs0 += __shfl_xor_sync(0xffffffffu, rs0, 2);
        rs1 += __shfl_xor_sync(0xffffffffu, rs1, 1);
        rs1 += __shfl_xor_sync(0xffffffffu, rs1, 2);
        lrow[0] = lrow[0] * a0 + rs0;
        lrow[1] = lrow[1] * a1 + rs1;

#pragma unroll
        for (int dt = 0; dt < 16; dt++) {
            o[dt][0] *= a0; o[dt][1] *= a0;
            o[dt][2] *= a1; o[dt][3] *= a1;
        }

        // ---- P to smem (tf32)
#pragma unroll
        for (int nt = 0; nt < 8; nt++) {
            uint32_t pb = psb + (uint32_t)((qb + g) * 68 + nt * 8 + t4 * 2) * 4;
            STS32(pb,     f2tf(sc[nt][0]));
            STS32(pb + 4, f2tf(sc[nt][1]));
            STS32(pb + 8 * 68 * 4,     f2tf(sc[nt][2]));
            STS32(pb + 8 * 68 * 4 + 4, f2tf(sc[nt][3]));
        }
        __syncwarp();

        // ---- store next V tile transposed (into other buffer)
        if (pre) {
#pragma unroll
            for (int l = 0; l < 8; l++) {
                int idx = t + l * 256;
                int r = idx >> 5, c = idx & 31;
                uint32_t b0 = su + VT_OFF + (b ^ 1) * VT_B +
                              (uint32_t)((c * 4) * 68 + r) * 4;
                STS32(b0,           f2tf(vr[l].x));
                STS32(b0 + 68 * 4,  f2tf(vr[l].y));
                STS32(b0 + 136 * 4, f2tf(vr[l].z));
                STS32(b0 + 204 * 4, f2tf(vr[l].w));
            }
        }

        // ---- O += P V
#pragma unroll
        for (int ks = 0; ks < 8; ks++) {
            unsigned pa[4];
            LDSM4(pa[0], pa[1], pa[2], pa[3], psb + opa + ks * 32);
#pragma unroll
            for (int p = 0; p < 8; p++) {
                unsigned vf0[2], vf1[2];
                LDSM4(vf0[0], vf0[1], vf1[0], vf1[1], vtb + ovv[p] + ks * 32);
                mma8(o[2 * p], pa, vf0);
                mma8(o[2 * p + 1], pa, vf1);
            }
        }

        if (pre) CP_WAIT0();
        __syncthreads();
    }

    float inv0 = 1.0f / lrow[0], inv1 = 1.0f / lrow[1];
    int s0 = qt * 128 + qb + g;
    float* dst0 = g_O + (size_t)s0 * DIMK + h * HDIM;
    float* dst1 = dst0 + (size_t)8 * DIMK;
#pragma unroll
    for (int dt = 0; dt < 16; dt++) {
        int d = dt * 8 + t4 * 2;
        *(float2*)(dst0 + d) = make_float2(o[dt][0] * inv0, o[dt][1] * inv0);
        *(float2*)(dst1 + d) = make_float2(o[dt][2] * inv1, o[dt][3] * inv1);
    }
}

// ---------------- launch ----------------------------------------------------
extern "C" void kernel_launch(void* const* d_in, const int* in_sizes, int n_in,
                              void* d_out, int out_size)
{
    const float* hid       = (const float*)d_in[0];
    const float* enc       = (const float*)d_in[1];
    const float* cosT      = (const float*)d_in[2];
    const float* sinT      = (const float*)d_in[3];
    const float* w_qkv     = (const float*)d_in[4];
    const float* b_qkv     = (const float*)d_in[5];
    const float* w_add     = (const float*)d_in[6];
    const float* b_add     = (const float*)d_in[7];
    const float* nq        = (const float*)d_in[8];
    const float* nk        = (const float*)d_in[9];
    const float* naq       = (const float*)d_in[10];
    const float* nak       = (const float*)d_in[11];
    const float* w_out     = (const float*)d_in[12];
    const float* b_out     = (const float*)d_in[13];
    const float* w_add_out = (const float*)d_in[14];
    const float* b_add_out = (const float*)d_in[15];
    float* out = (float*)d_out;

    static bool attr_done = false;
    if (!attr_done) {
        cudaFuncSetAttribute(gemm_qkv_kernel,
            cudaFuncAttributeMaxDynamicSharedMemorySize, GEMM_SMEM_BYTES);
        cudaFuncSetAttribute(gemm_out_kernel,
            cudaFuncAttributeMaxDynamicSharedMemorySize, GEMM_SMEM_BYTES);
        cudaFuncSetAttribute(flash_v3_kernel,
            cudaFuncAttributeMaxDynamicSharedMemorySize, FLASH_SMEM_BYTES);
        attr_done = true;
    }

    gemm_qkv_kernel<<<dim3(S_TOT / 128, E3 / 256), 256, GEMM_SMEM_BYTES>>>(
        hid, enc, w_qkv, b_qkv, w_add, b_add);

    norm_rope_kernel<<<dim3(S_TOT, NHEADS), 128>>>(cosT, sinT, nq, nk, naq, nak);

    flash_v3_kernel<<<dim3(S_TOT / 128, NHEADS), 256, FLASH_SMEM_BYTES>>>();

    gemm_out_kernel<<<dim3(S_TOT / 128, DIMK / 256), 256, GEMM_SMEM_BYTES>>>(
        w_out, b_out, w_add_out, b_add_out, out);
}